// round 4
// baseline (speedup 1.0000x reference)
#include <cuda_runtime.h>
#include <cuda_bf16.h>
#include <cstdint>

// B=128, U=64, A=64. One CTA = one (b,a) slice: 64ch x 64u.
// GEMMs on tensor cores: bf16 mma.sync m16n8k16, 3-term hi/lo fp32 emulation.
// Intermediates g_r/g_msgs: fp32 [ba][c][u].

#define NBA 8192

__device__ float g_cgT[128 * 64 * 64];                 // [b][a][u]
__device__ float g_msgs[(size_t)128 * 64 * 4096];      // [ba][c][u]
__device__ float g_r[(size_t)128 * 64 * 4096];         // [ba][c][u]
__device__ float g_sums[128 * 4096];                   // [b][c][u]  (full a-sum)
__device__ __align__(16) uint32_t g_wfrag[96256];      // packed bf16 A-fragments

// fragment-block offsets (u32). count per layer = KB*1024
#define OFF_PHI1_W1F 0
#define OFF_PHI1_W2F 1024
#define OFF_PHIK_W1F 5120
#define OFF_PHIK_W2F 25600
#define OFF_G1_W1F   41984
#define OFF_G1_W2F   47104
#define OFF_GK_W1F   51200
#define OFF_GK_W2F   75776
#define OFF_G5_W1F   88064

__device__ __forceinline__ uint32_t pack2(float a, float b) {
    uint32_t la = (uint32_t)__bfloat16_as_ushort(__float2bfloat16_rn(a));
    uint32_t lb = (uint32_t)__bfloat16_as_ushort(__float2bfloat16_rn(b));
    return la | (lb << 16);
}
__device__ __forceinline__ void split1(float v, float& hi, float& lo) {
    hi = __bfloat162float(__float2bfloat16_rn(v));
    lo = v - hi;
}
__device__ __forceinline__ void mma16816(float d[4], const uint4& a, uint32_t b0, uint32_t b1) {
    asm volatile("mma.sync.aligned.m16n8k16.row.col.f32.bf16.bf16.f32 "
                 "{%0,%1,%2,%3}, {%4,%5,%6,%7}, {%8,%9}, {%0,%1,%2,%3};\n"
                 : "+f"(d[0]), "+f"(d[1]), "+f"(d[2]), "+f"(d[3])
                 : "r"(a.x), "r"(a.y), "r"(a.z), "r"(a.w), "r"(b0), "r"(b1));
}

// ---------------- prep: build bf16 hi/lo A-fragments ------------------------
// frag u32 index e: strip(4) | kt(KB) | plane(2) | lane(32) | j(4)
// j: bit0 -> row+8, bit1 -> k+8.  row o = strip*16 + lane/4 (+8); k0 = kt*16 + (lane%4)*2 (+8)
// types: 0: C=64 direct; 1: C=65 (col0=cg -> mapped to c=64; cols1..64 -> c=0..63; pad 0)
//        2: C=128 direct; 3: folded phi1 (c==0 -> W[o][0]+W[o][1], else 0)
__global__ void prep_kernel(const float* __restrict__ phi1W1, const float* __restrict__ phi1W2,
                            const float* __restrict__ phiKW1, const float* __restrict__ phiKW2,
                            const float* __restrict__ g1W1,   const float* __restrict__ g1W2,
                            const float* __restrict__ gKW1,   const float* __restrict__ gKW2,
                            const float* __restrict__ g5W1) {
    const int id = blockIdx.x;
    const float* src; int off, KB, type;
    if (id == 0)       { src = phi1W1;              off = OFF_PHI1_W1F;            KB = 1; type = 3; }
    else if (id == 1)  { src = phi1W2;              off = OFF_PHI1_W2F;            KB = 4; type = 0; }
    else if (id < 6)   { int i = id - 2;  src = phiKW1 + i * 64 * 65;  off = OFF_PHIK_W1F + i * 5120; KB = 5; type = 1; }
    else if (id < 10)  { int i = id - 6;  src = phiKW2 + i * 4096;     off = OFF_PHIK_W2F + i * 4096; KB = 4; type = 0; }
    else if (id == 10) { src = g1W1;                off = OFF_G1_W1F;              KB = 5; type = 1; }
    else if (id == 11) { src = g1W2;                off = OFF_G1_W2F;              KB = 4; type = 0; }
    else if (id < 15)  { int i = id - 12; src = gKW1 + i * 64 * 128;   off = OFF_GK_W1F + i * 8192;   KB = 8; type = 2; }
    else if (id < 18)  { int i = id - 15; src = gKW2 + i * 4096;       off = OFF_GK_W2F + i * 4096;   KB = 4; type = 0; }
    else               { src = g5W1;                off = OFF_G5_W1F;              KB = 8; type = 2; }

    const int total = KB * 1024;
    for (int e = threadIdx.x; e < total; e += blockDim.x) {
        int strip = e / (KB * 256);
        int rem   = e % (KB * 256);
        int kt = rem / 256;
        int r2 = rem % 256;
        int plane = r2 >> 7;
        int r3 = r2 & 127;
        int lane = r3 >> 2, j = r3 & 3;
        int o  = strip * 16 + (lane >> 2) + 8 * (j & 1);
        int k0 = kt * 16 + (lane & 3) * 2 + 8 * (j >> 1);
        float w0, w1;
        if (type == 0)      { w0 = src[o * 64 + k0];  w1 = src[o * 64 + k0 + 1]; }
        else if (type == 2) { w0 = src[o * 128 + k0]; w1 = src[o * 128 + k0 + 1]; }
        else if (type == 1) {
            auto fetch = [&](int c) -> float {
                if (c < 64) return src[o * 65 + 1 + c];
                if (c == 64) return src[o * 65];
                return 0.0f;
            };
            w0 = fetch(k0); w1 = fetch(k0 + 1);
        } else { // folded phi1
            w0 = (k0 == 0) ? (src[o * 2] + src[o * 2 + 1]) : 0.0f;
            w1 = 0.0f;
        }
        float h0, l0, h1, l1; split1(w0, h0, l0); split1(w1, h1, l1);
        g_wfrag[off + e] = plane ? pack2(l0, l1) : pack2(h0, h1);
    }
}

// ---------------- cg transpose: (B,U,A) -> [b][a][u] ------------------------
__global__ void cgt_kernel(const float* __restrict__ cg) {
    const int b = blockIdx.x;
    for (int j = threadIdx.x; j < 4096; j += 256) {
        int a = j >> 6, u = j & 63;
        g_cgT[b * 4096 + j] = cg[b * 4096 + u * 64 + a];
    }
}

// ---------------- full sum over a of msgs -----------------------------------
__global__ void asum_kernel() {
    const int b = blockIdx.x >> 4;
    const int e = (blockIdx.x & 15) * 256 + threadIdx.x;   // c*64+u
    const float* p = g_msgs + (size_t)b * 262144 + e;
    float s = 0.0f;
#pragma unroll 8
    for (int a = 0; a < 64; ++a) s += p[(size_t)a * 4096];
    g_sums[b * 4096 + e] = s;
}

// ---------------- X value per mode ------------------------------------------
template<int MODE>
__device__ __forceinline__ float xval(int c, int u, const float* cgp, const float* rp,
                                      const float* mp, const float* sp) {
    const float inv = 1.0f / 63.0f;
    if (MODE == 0) { return (c == 0) ? cgp[u] : 0.0f; }
    if (MODE == 1) { if (c < 64) return rp[c * 64 + u]; if (c == 64) return cgp[u]; return 0.0f; }
    if (MODE == 2) { if (c < 64) return (sp[c * 64 + u] - mp[c * 64 + u]) * inv;
                     if (c == 64) return cgp[u]; return 0.0f; }
    // MODE 3
    if (c < 64) return rp[c * 64 + u];
    return (sp[(c - 64) * 64 + u] - mp[(c - 64) * 64 + u]) * inv;
}

// ---------------- layer kernel ----------------------------------------------
// MODE: 0 phi1, 1 phiK, 2 gamma1, 3 gammaK.  RELU2: relu before post on conv2
// (gamma). FINAL: conv2 is 1x64 GEMV to dout.
template<int KB1, int MODE, bool RELU2, bool FINAL>
__global__ void __launch_bounds__(128) layer_kernel(const float* __restrict__ b1v,
                                                    const float* __restrict__ b2v,
                                                    int w1off, int w2off,
                                                    const float* __restrict__ w2raw,
                                                    float* __restrict__ dout) {
    extern __shared__ uint32_t sm[];
    uint32_t* sW1f = sm;                         // KB1*1024
    uint32_t* sW2f = sW1f + KB1 * 1024;          // 4096
    uint32_t* sXh  = sW2f + 4096;                // KB1*8*72
    uint32_t* sXl  = sXh + KB1 * 8 * 72;         // KB1*8*72
    float*    sH   = (float*)(sXl + KB1 * 8 * 72); // 64*65

    const int t = threadIdx.x;
    const int ba = blockIdx.x;
    const int b = ba >> 6;
    const int warp = t >> 5, lane = t & 31, q = lane & 3, g = lane >> 2;
    const float inv = 1.0f / 63.0f;

    // copy weight fragments
    {
        const uint4* gw1 = (const uint4*)(g_wfrag + w1off);
        uint4* d1 = (uint4*)sW1f;
        for (int i = t; i < KB1 * 256; i += 128) d1[i] = gw1[i];
        if (!FINAL) {
            const uint4* gw2 = (const uint4*)(g_wfrag + w2off);
            uint4* d2 = (uint4*)sW2f;
#pragma unroll
            for (int k = 0; k < 8; ++k) d2[t + k * 128] = gw2[t + k * 128];
        }
    }

    // pack X (hi/lo bf16 pairs along channel, row stride 72)
    {
        const float* cgp = g_cgT + ba * 64;
        const float* rp  = g_r + (size_t)ba * 4096;
        const float* mp  = g_msgs + (size_t)ba * 4096;
        const float* sp  = g_sums + b * 4096;
        constexpr int C2 = KB1 * 8;
        for (int idx = t; idx < C2 * 64; idx += 128) {
            int c2 = idx >> 6, u = idx & 63;
            float v0 = xval<MODE>(2 * c2, u, cgp, rp, mp, sp);
            float v1 = xval<MODE>(2 * c2 + 1, u, cgp, rp, mp, sp);
            float h0, l0, h1, l1; split1(v0, h0, l0); split1(v1, h1, l1);
            sXh[c2 * 72 + u] = pack2(h0, h1);
            sXl[c2 * 72 + u] = pack2(l0, l1);
        }
    }
    __syncthreads();

    const int o_r = warp * 16 + g, o_r8 = o_r + 8;

    // ---- conv1 ----
    float acc[8][4];
    {
        float bA = __ldg(b1v + o_r), bB = __ldg(b1v + o_r8);
#pragma unroll
        for (int nt = 0; nt < 8; ++nt) { acc[nt][0] = bA; acc[nt][1] = bA; acc[nt][2] = bB; acc[nt][3] = bB; }
        const uint4* A1 = (const uint4*)sW1f + warp * (KB1 * 64);
#pragma unroll
        for (int kt = 0; kt < KB1; ++kt) {
            uint4 Ah = A1[kt * 64 + lane];
            uint4 Al = A1[kt * 64 + 32 + lane];
            const uint32_t* xh0 = sXh + (kt * 8 + q) * 72 + g;
            const uint32_t* xh1 = sXh + (kt * 8 + 4 + q) * 72 + g;
            const uint32_t* xl0 = sXl + (kt * 8 + q) * 72 + g;
            const uint32_t* xl1 = sXl + (kt * 8 + 4 + q) * 72 + g;
#pragma unroll
            for (int nt = 0; nt < 8; ++nt) {
                uint32_t bh0 = xh0[nt * 8], bh1 = xh1[nt * 8];
                uint32_t bl0 = xl0[nt * 8], bl1 = xl1[nt * 8];
                mma16816(acc[nt], Ah, bh0, bh1);
                mma16816(acc[nt], Ah, bl0, bl1);
                mma16816(acc[nt], Al, bh0, bh1);
            }
        }
    }
    // relu + colsum + post -> sH
    {
#pragma unroll
        for (int nt = 0; nt < 8; ++nt)
#pragma unroll
            for (int j = 0; j < 4; ++j) acc[nt][j] = fmaxf(acc[nt][j], 0.0f);
        float Sr = 0.0f, Sr8 = 0.0f;
#pragma unroll
        for (int nt = 0; nt < 8; ++nt) { Sr += acc[nt][0] + acc[nt][1]; Sr8 += acc[nt][2] + acc[nt][3]; }
        Sr  += __shfl_xor_sync(0xffffffffu, Sr, 1);  Sr  += __shfl_xor_sync(0xffffffffu, Sr, 2);
        Sr8 += __shfl_xor_sync(0xffffffffu, Sr8, 1); Sr8 += __shfl_xor_sync(0xffffffffu, Sr8, 2);
#pragma unroll
        for (int nt = 0; nt < 8; ++nt) {
            int u0 = nt * 8 + q * 2;
            if (warp >= 2) {
                sH[o_r * 65 + u0]      = (Sr - acc[nt][0]) * inv;
                sH[o_r * 65 + u0 + 1]  = (Sr - acc[nt][1]) * inv;
                sH[o_r8 * 65 + u0]     = (Sr8 - acc[nt][2]) * inv;
                sH[o_r8 * 65 + u0 + 1] = (Sr8 - acc[nt][3]) * inv;
            } else {
                sH[o_r * 65 + u0]      = acc[nt][0];
                sH[o_r * 65 + u0 + 1]  = acc[nt][1];
                sH[o_r8 * 65 + u0]     = acc[nt][2];
                sH[o_r8 * 65 + u0 + 1] = acc[nt][3];
            }
        }
    }
    __syncthreads();

    if (!FINAL) {
        // repack H from sH into sXh/sXl (32 c2 rows)
        for (int idx = t; idx < 32 * 64; idx += 128) {
            int c2 = idx >> 6, u = idx & 63;
            float v0 = sH[(2 * c2) * 65 + u];
            float v1 = sH[(2 * c2 + 1) * 65 + u];
            float h0, l0, h1, l1; split1(v0, h0, l0); split1(v1, h1, l1);
            sXh[c2 * 72 + u] = pack2(h0, h1);
            sXl[c2 * 72 + u] = pack2(l0, l1);
        }
        __syncthreads();

        // ---- conv2 (KB=4) ----
        float a2[8][4];
        float bA = __ldg(b2v + o_r), bB = __ldg(b2v + o_r8);
#pragma unroll
        for (int nt = 0; nt < 8; ++nt) { a2[nt][0] = bA; a2[nt][1] = bA; a2[nt][2] = bB; a2[nt][3] = bB; }
        const uint4* A2 = (const uint4*)sW2f + warp * 256;
#pragma unroll
        for (int kt = 0; kt < 4; ++kt) {
            uint4 Ah = A2[kt * 64 + lane];
            uint4 Al = A2[kt * 64 + 32 + lane];
            const uint32_t* xh0 = sXh + (kt * 8 + q) * 72 + g;
            const uint32_t* xh1 = sXh + (kt * 8 + 4 + q) * 72 + g;
            const uint32_t* xl0 = sXl + (kt * 8 + q) * 72 + g;
            const uint32_t* xl1 = sXl + (kt * 8 + 4 + q) * 72 + g;
#pragma unroll
            for (int nt = 0; nt < 8; ++nt) {
                uint32_t bh0 = xh0[nt * 8], bh1 = xh1[nt * 8];
                uint32_t bl0 = xl0[nt * 8], bl1 = xl1[nt * 8];
                mma16816(a2[nt], Ah, bh0, bh1);
                mma16816(a2[nt], Ah, bl0, bl1);
                mma16816(a2[nt], Al, bh0, bh1);
            }
        }
        if (RELU2) {
#pragma unroll
            for (int nt = 0; nt < 8; ++nt)
#pragma unroll
                for (int j = 0; j < 4; ++j) a2[nt][j] = fmaxf(a2[nt][j], 0.0f);
        }
        float Sr = 0.0f, Sr8 = 0.0f;
#pragma unroll
        for (int nt = 0; nt < 8; ++nt) { Sr += a2[nt][0] + a2[nt][1]; Sr8 += a2[nt][2] + a2[nt][3]; }
        Sr  += __shfl_xor_sync(0xffffffffu, Sr, 1);  Sr  += __shfl_xor_sync(0xffffffffu, Sr, 2);
        Sr8 += __shfl_xor_sync(0xffffffffu, Sr8, 1); Sr8 += __shfl_xor_sync(0xffffffffu, Sr8, 2);

        float* gout = (RELU2 ? g_r : g_msgs) + (size_t)ba * 4096;
#pragma unroll
        for (int nt = 0; nt < 8; ++nt) {
            int u0 = nt * 8 + q * 2;
            float2 vA, vB;
            if (warp >= 2) {
                vA.x = (Sr - a2[nt][0]) * inv;  vA.y = (Sr - a2[nt][1]) * inv;
                vB.x = (Sr8 - a2[nt][2]) * inv; vB.y = (Sr8 - a2[nt][3]) * inv;
            } else {
                vA.x = a2[nt][0]; vA.y = a2[nt][1];
                vB.x = a2[nt][2]; vB.y = a2[nt][3];
            }
            *reinterpret_cast<float2*>(gout + o_r * 64 + u0)  = vA;
            *reinterpret_cast<float2*>(gout + o_r8 * 64 + u0) = vB;
        }
    } else {
        // final conv2: 1x64 GEMV over sH
        const int u = t >> 1, half = t & 1;
        float s = 0.0f;
        const int c0 = half * 32;
#pragma unroll 8
        for (int c = c0; c < c0 + 32; ++c)
            s = fmaf(__ldg(w2raw + c), sH[c * 65 + u], s);
        s += __shfl_xor_sync(0xffffffffu, s, 1);
        if (half == 0) {
            const int a = ba & 63;
            dout[b * 4096 + u * 64 + a] = s + __ldg(b2v);
        }
    }
}

// ---------------- launch -----------------------------------------------------
extern "C" void kernel_launch(void* const* d_in, const int* in_sizes, int n_in,
                              void* d_out, int out_size) {
    (void)in_sizes; (void)n_in; (void)out_size;
    const float* cg      = (const float*)d_in[0];
    const float* phi1_W1 = (const float*)d_in[1];
    const float* phi1_b1 = (const float*)d_in[2];
    const float* phi1_W2 = (const float*)d_in[3];
    const float* phi1_b2 = (const float*)d_in[4];
    const float* phiK_W1 = (const float*)d_in[5];
    const float* phiK_b1 = (const float*)d_in[6];
    const float* phiK_W2 = (const float*)d_in[7];
    const float* phiK_b2 = (const float*)d_in[8];
    const float* g1_W1   = (const float*)d_in[9];
    const float* g1_b1   = (const float*)d_in[10];
    const float* g1_W2   = (const float*)d_in[11];
    const float* g1_b2   = (const float*)d_in[12];
    const float* gK_W1   = (const float*)d_in[13];
    const float* gK_b1   = (const float*)d_in[14];
    const float* gK_W2   = (const float*)d_in[15];
    const float* gK_b2   = (const float*)d_in[16];
    const float* g5_W1   = (const float*)d_in[17];
    const float* g5_b1   = (const float*)d_in[18];
    const float* g5_W2   = (const float*)d_in[19];
    const float* g5_b2   = (const float*)d_in[20];
    float* out = (float*)d_out;

    // smem bytes = KB1*8704 + 33024
    const int SM1 = 1 * 8704 + 33024;   // phi1
    const int SM5 = 5 * 8704 + 33024;   // phiK / gamma1
    const int SM8 = 8 * 8704 + 33024;   // gammaK / gamma5

    cudaFuncSetAttribute(layer_kernel<1, 0, false, false>, cudaFuncAttributeMaxDynamicSharedMemorySize, SM1);
    cudaFuncSetAttribute(layer_kernel<5, 1, false, false>, cudaFuncAttributeMaxDynamicSharedMemorySize, SM5);
    cudaFuncSetAttribute(layer_kernel<5, 2, true,  false>, cudaFuncAttributeMaxDynamicSharedMemorySize, SM5);
    cudaFuncSetAttribute(layer_kernel<8, 3, true,  false>, cudaFuncAttributeMaxDynamicSharedMemorySize, SM8);
    cudaFuncSetAttribute(layer_kernel<8, 3, true,  true>,  cudaFuncAttributeMaxDynamicSharedMemorySize, SM8);

    prep_kernel<<<19, 256>>>(phi1_W1, phi1_W2, phiK_W1, phiK_W2, g1_W1, g1_W2, gK_W1, gK_W2, g5_W1);
    cgt_kernel<<<128, 256>>>(cg);

    // iteration 0
    layer_kernel<1, 0, false, false><<<NBA, 128, SM1>>>(phi1_b1, phi1_b2, OFF_PHI1_W1F, OFF_PHI1_W2F, nullptr, nullptr);
    asum_kernel<<<2048, 256>>>();
    layer_kernel<5, 2, true, false><<<NBA, 128, SM5>>>(g1_b1, g1_b2, OFF_G1_W1F, OFF_G1_W2F, nullptr, nullptr);

    // iterations 1..4
    for (int i = 0; i < 4; ++i) {
        layer_kernel<5, 1, false, false><<<NBA, 128, SM5>>>(phiK_b1 + i * 64, phiK_b2 + i * 64,
                                                            OFF_PHIK_W1F + i * 5120, OFF_PHIK_W2F + i * 4096,
                                                            nullptr, nullptr);
        asum_kernel<<<2048, 256>>>();
        if (i < 3) {
            layer_kernel<8, 3, true, false><<<NBA, 128, SM8>>>(gK_b1 + i * 64, gK_b2 + i * 64,
                                                               OFF_GK_W1F + i * 8192, OFF_GK_W2F + i * 4096,
                                                               nullptr, nullptr);
        } else {
            layer_kernel<8, 3, true, true><<<NBA, 128, SM8>>>(g5_b1, g5_b2,
                                                              OFF_G5_W1F, 0, g5_W2, out);
        }
    }
}

// round 5
// speedup vs baseline: 1.1918x; 1.1918x over previous
#include <cuda_runtime.h>
#include <cuda_bf16.h>
#include <cstdint>

// B=128, U=64, A=64. One CTA = one (b,a) slice: 64ch x 64u, 256 threads.
// GEMMs: bf16 mma.sync m16n8k16, 3-term hi/lo fp32 emulation.
// Intermediates g_r/g_msgs: fp32 [ba][c][u].

#define NBA 8192

__device__ float g_cgT[128 * 64 * 64];                 // [b][a][u]
__device__ float g_msgs[(size_t)128 * 64 * 4096];      // [ba][c][u]
__device__ float g_r[(size_t)128 * 64 * 4096];         // [ba][c][u]
__device__ float g_sums[128 * 4096];                   // [b][c][u]  (full a-sum)
__device__ __align__(16) uint32_t g_wfrag[96256];      // packed bf16 A-fragments

#define OFF_PHI1_W1F 0
#define OFF_PHI1_W2F 1024
#define OFF_PHIK_W1F 5120
#define OFF_PHIK_W2F 25600
#define OFF_G1_W1F   41984
#define OFF_G1_W2F   47104
#define OFF_GK_W1F   51200
#define OFF_GK_W2F   75776
#define OFF_G5_W1F   88064

__device__ __forceinline__ uint32_t pack2(float a, float b) {
    uint32_t la = (uint32_t)__bfloat16_as_ushort(__float2bfloat16_rn(a));
    uint32_t lb = (uint32_t)__bfloat16_as_ushort(__float2bfloat16_rn(b));
    return la | (lb << 16);
}
__device__ __forceinline__ void split1(float v, float& hi, float& lo) {
    hi = __bfloat162float(__float2bfloat16_rn(v));
    lo = v - hi;
}
__device__ __forceinline__ void mma16816(float d[4], const uint4& a, uint32_t b0, uint32_t b1) {
    asm volatile("mma.sync.aligned.m16n8k16.row.col.f32.bf16.bf16.f32 "
                 "{%0,%1,%2,%3}, {%4,%5,%6,%7}, {%8,%9}, {%0,%1,%2,%3};\n"
                 : "+f"(d[0]), "+f"(d[1]), "+f"(d[2]), "+f"(d[3])
                 : "r"(a.x), "r"(a.y), "r"(a.z), "r"(a.w), "r"(b0), "r"(b1));
}

// ---------------- prep: build bf16 hi/lo A-fragments (unchanged layout) -----
__global__ void prep_kernel(const float* __restrict__ phi1W1, const float* __restrict__ phi1W2,
                            const float* __restrict__ phiKW1, const float* __restrict__ phiKW2,
                            const float* __restrict__ g1W1,   const float* __restrict__ g1W2,
                            const float* __restrict__ gKW1,   const float* __restrict__ gKW2,
                            const float* __restrict__ g5W1) {
    const int id = blockIdx.x;
    const float* src; int off, KB, type;
    if (id == 0)       { src = phi1W1;              off = OFF_PHI1_W1F;            KB = 1; type = 3; }
    else if (id == 1)  { src = phi1W2;              off = OFF_PHI1_W2F;            KB = 4; type = 0; }
    else if (id < 6)   { int i = id - 2;  src = phiKW1 + i * 64 * 65;  off = OFF_PHIK_W1F + i * 5120; KB = 5; type = 1; }
    else if (id < 10)  { int i = id - 6;  src = phiKW2 + i * 4096;     off = OFF_PHIK_W2F + i * 4096; KB = 4; type = 0; }
    else if (id == 10) { src = g1W1;                off = OFF_G1_W1F;              KB = 5; type = 1; }
    else if (id == 11) { src = g1W2;                off = OFF_G1_W2F;              KB = 4; type = 0; }
    else if (id < 15)  { int i = id - 12; src = gKW1 + i * 64 * 128;   off = OFF_GK_W1F + i * 8192;   KB = 8; type = 2; }
    else if (id < 18)  { int i = id - 15; src = gKW2 + i * 4096;       off = OFF_GK_W2F + i * 4096;   KB = 4; type = 0; }
    else               { src = g5W1;                off = OFF_G5_W1F;              KB = 8; type = 2; }

    const int total = KB * 1024;
    for (int e = threadIdx.x; e < total; e += blockDim.x) {
        int strip = e / (KB * 256);
        int rem   = e % (KB * 256);
        int kt = rem / 256;
        int r2 = rem % 256;
        int plane = r2 >> 7;
        int r3 = r2 & 127;
        int lane = r3 >> 2, j = r3 & 3;
        int o  = strip * 16 + (lane >> 2) + 8 * (j & 1);
        int k0 = kt * 16 + (lane & 3) * 2 + 8 * (j >> 1);
        float w0, w1;
        if (type == 0)      { w0 = src[o * 64 + k0];  w1 = src[o * 64 + k0 + 1]; }
        else if (type == 2) { w0 = src[o * 128 + k0]; w1 = src[o * 128 + k0 + 1]; }
        else if (type == 1) {
            auto fetch = [&](int c) -> float {
                if (c < 64) return src[o * 65 + 1 + c];
                if (c == 64) return src[o * 65];
                return 0.0f;
            };
            w0 = fetch(k0); w1 = fetch(k0 + 1);
        } else {
            w0 = (k0 == 0) ? (src[o * 2] + src[o * 2 + 1]) : 0.0f;
            w1 = 0.0f;
        }
        float h0, l0, h1, l1; split1(w0, h0, l0); split1(w1, h1, l1);
        g_wfrag[off + e] = plane ? pack2(l0, l1) : pack2(h0, h1);
    }
}

// ---------------- cg transpose ------------------------------------------------
__global__ void cgt_kernel(const float* __restrict__ cg) {
    const int b = blockIdx.x;
    for (int j = threadIdx.x; j < 4096; j += 256) {
        int a = j >> 6, u = j & 63;
        g_cgT[b * 4096 + j] = cg[b * 4096 + u * 64 + a];
    }
}

// ---------------- full sum over a of msgs -------------------------------------
__global__ void asum_kernel() {
    const int b = blockIdx.x >> 4;
    const int e = (blockIdx.x & 15) * 256 + threadIdx.x;
    const float* p = g_msgs + (size_t)b * 262144 + e;
    float s = 0.0f;
#pragma unroll 8
    for (int a = 0; a < 64; ++a) s += p[(size_t)a * 4096];
    g_sums[b * 4096 + e] = s;
}

// ---------------- X value per mode --------------------------------------------
template<int MODE>
__device__ __forceinline__ float xval(int c, int u, const float* cgp, const float* rp,
                                      const float* mp, const float* sp) {
    const float inv = 1.0f / 63.0f;
    if (MODE == 0) { return (c == 0) ? cgp[u] : 0.0f; }
    if (MODE == 1) { if (c < 64) return rp[c * 64 + u]; if (c == 64) return cgp[u]; return 0.0f; }
    if (MODE == 2) { if (c < 64) return (sp[c * 64 + u] - mp[c * 64 + u]) * inv;
                     if (c == 64) return cgp[u]; return 0.0f; }
    if (c < 64) return rp[c * 64 + u];
    return (sp[(c - 64) * 64 + u] - mp[(c - 64) * 64 + u]) * inv;
}

// ---------------- mma block: 12 mma over one kt, B loads hoisted --------------
__device__ __forceinline__ void mma_kt(float acc[4][4], const uint4* __restrict__ A,
                                       const uint32_t* __restrict__ sXh,
                                       const uint32_t* __restrict__ sXl,
                                       int kt, int q, int gub) {
    uint4 Ah = A[kt * 64 + (q | ((gub & 31) & 0))];  // placeholder avoided below
    (void)Ah;
}

// ---------------- layer kernel ------------------------------------------------
// 256 threads: warp w: strip s = w>>1 (rows s*16..+15), half h2 = w&1 (u += h2*32)
template<int KB1, int MODE, bool RELU2, bool FINAL>
__global__ void __launch_bounds__(256) layer_kernel(const float* __restrict__ b1v,
                                                    const float* __restrict__ b2v,
                                                    int w1off, int w2off,
                                                    const float* __restrict__ w2raw,
                                                    float* __restrict__ dout) {
    constexpr int XR = (KB1 * 8 < 32) ? 32 : KB1 * 8;
    extern __shared__ uint32_t sm[];
    uint32_t* sW1f = sm;                         // KB1*1024
    uint32_t* sW2f = sW1f + KB1 * 1024;          // 4096
    uint32_t* sXh  = sW2f + 4096;                // XR*72
    uint32_t* sXl  = sXh + XR * 72;              // XR*72
    float*    sH   = (float*)(sXl + XR * 72);    // 64*66
    float*    sS   = sH + 64 * 66;               // 2*80

    const int t = threadIdx.x;
    const int ba = blockIdx.x;
    const int b = ba >> 6;
    const int warp = t >> 5, lane = t & 31, q = lane & 3, g = lane >> 2;
    const int s = warp >> 1, h2 = warp & 1;
    const int ub = h2 * 32;
    const float inv = 1.0f / 63.0f;

    // load weight fragments
    {
        const uint4* gw1 = (const uint4*)(g_wfrag + w1off);
        uint4* d1 = (uint4*)sW1f;
        for (int i = t; i < KB1 * 256; i += 256) d1[i] = gw1[i];
        if (!FINAL) {
            const uint4* gw2 = (const uint4*)(g_wfrag + w2off);
            uint4* d2 = (uint4*)sW2f;
#pragma unroll
            for (int k = 0; k < 4; ++k) d2[t + k * 256] = gw2[t + k * 256];
        }
    }
    // pack X
    {
        const float* cgp = g_cgT + ba * 64;
        const float* rp  = g_r + (size_t)ba * 4096;
        const float* mp  = g_msgs + (size_t)ba * 4096;
        const float* sp  = g_sums + b * 4096;
        constexpr int C2 = KB1 * 8;
        for (int idx = t; idx < C2 * 64; idx += 256) {
            int c2 = idx >> 6, u = idx & 63;
            float v0 = xval<MODE>(2 * c2, u, cgp, rp, mp, sp);
            float v1 = xval<MODE>(2 * c2 + 1, u, cgp, rp, mp, sp);
            float h0, l0, h1, l1; split1(v0, h0, l0); split1(v1, h1, l1);
            sXh[c2 * 72 + u] = pack2(h0, h1);
            sXl[c2 * 72 + u] = pack2(l0, l1);
        }
    }
    __syncthreads();

    const int o_r = s * 16 + g, o_r8 = o_r + 8;

    // ---- conv1 ----
    float acc[4][4];
    {
        float bA = __ldg(b1v + o_r), bB = __ldg(b1v + o_r8);
#pragma unroll
        for (int nt = 0; nt < 4; ++nt) { acc[nt][0] = bA; acc[nt][1] = bA; acc[nt][2] = bB; acc[nt][3] = bB; }
        const uint4* A1 = (const uint4*)sW1f + s * (KB1 * 64);
#pragma unroll
        for (int kt = 0; kt < KB1; ++kt) {
            uint4 Ah = A1[kt * 64 + lane];
            uint4 Al = A1[kt * 64 + 32 + lane];
            const uint32_t* xh0 = sXh + (kt * 8 + q) * 72 + ub + g;
            const uint32_t* xh1 = sXh + (kt * 8 + 4 + q) * 72 + ub + g;
            const uint32_t* xl0 = sXl + (kt * 8 + q) * 72 + ub + g;
            const uint32_t* xl1 = sXl + (kt * 8 + 4 + q) * 72 + ub + g;
            uint32_t bh0[4], bh1[4], bl0[4], bl1[4];
#pragma unroll
            for (int nt = 0; nt < 4; ++nt) {
                bh0[nt] = xh0[nt * 8]; bh1[nt] = xh1[nt * 8];
                bl0[nt] = xl0[nt * 8]; bl1[nt] = xl1[nt * 8];
            }
#pragma unroll
            for (int nt = 0; nt < 4; ++nt) {
                mma16816(acc[nt], Ah, bh0[nt], bh1[nt]);
                mma16816(acc[nt], Ah, bl0[nt], bl1[nt]);
                mma16816(acc[nt], Al, bh0[nt], bh1[nt]);
            }
        }
    }
    // relu + colsum + post -> sH
    {
#pragma unroll
        for (int nt = 0; nt < 4; ++nt)
#pragma unroll
            for (int j = 0; j < 4; ++j) acc[nt][j] = fmaxf(acc[nt][j], 0.0f);
        float sA = 0.0f, sB = 0.0f;
#pragma unroll
        for (int nt = 0; nt < 4; ++nt) { sA += acc[nt][0] + acc[nt][1]; sB += acc[nt][2] + acc[nt][3]; }
        sA += __shfl_xor_sync(0xffffffffu, sA, 1); sA += __shfl_xor_sync(0xffffffffu, sA, 2);
        sB += __shfl_xor_sync(0xffffffffu, sB, 1); sB += __shfl_xor_sync(0xffffffffu, sB, 2);
        if (q == 0) { sS[h2 * 80 + o_r] = sA; sS[h2 * 80 + o_r8] = sB; }
        __syncthreads();
        float SA = sS[o_r] + sS[80 + o_r];
        float SB = sS[o_r8] + sS[80 + o_r8];
#pragma unroll
        for (int nt = 0; nt < 4; ++nt) {
            int u0 = ub + nt * 8 + q * 2;
            float2 vA, vB;
            if (s >= 2) {
                vA.x = (SA - acc[nt][0]) * inv; vA.y = (SA - acc[nt][1]) * inv;
                vB.x = (SB - acc[nt][2]) * inv; vB.y = (SB - acc[nt][3]) * inv;
            } else {
                vA.x = acc[nt][0]; vA.y = acc[nt][1];
                vB.x = acc[nt][2]; vB.y = acc[nt][3];
            }
            *reinterpret_cast<float2*>(sH + o_r * 66 + u0)  = vA;
            *reinterpret_cast<float2*>(sH + o_r8 * 66 + u0) = vB;
        }
    }
    __syncthreads();

    if (!FINAL) {
        // repack H -> sXh/sXl rows 0..31
        for (int idx = t; idx < 32 * 64; idx += 256) {
            int c2 = idx >> 6, u = idx & 63;
            float v0 = sH[(2 * c2) * 66 + u];
            float v1 = sH[(2 * c2 + 1) * 66 + u];
            float h0, l0, h1, l1; split1(v0, h0, l0); split1(v1, h1, l1);
            sXh[c2 * 72 + u] = pack2(h0, h1);
            sXl[c2 * 72 + u] = pack2(l0, l1);
        }
        __syncthreads();

        // ---- conv2 (KB=4) ----
        float a2[4][4];
        float bA = __ldg(b2v + o_r), bB = __ldg(b2v + o_r8);
#pragma unroll
        for (int nt = 0; nt < 4; ++nt) { a2[nt][0] = bA; a2[nt][1] = bA; a2[nt][2] = bB; a2[nt][3] = bB; }
        const uint4* A2 = (const uint4*)sW2f + s * 256;
#pragma unroll
        for (int kt = 0; kt < 4; ++kt) {
            uint4 Ah = A2[kt * 64 + lane];
            uint4 Al = A2[kt * 64 + 32 + lane];
            const uint32_t* xh0 = sXh + (kt * 8 + q) * 72 + ub + g;
            const uint32_t* xh1 = sXh + (kt * 8 + 4 + q) * 72 + ub + g;
            const uint32_t* xl0 = sXl + (kt * 8 + q) * 72 + ub + g;
            const uint32_t* xl1 = sXl + (kt * 8 + 4 + q) * 72 + ub + g;
            uint32_t bh0[4], bh1[4], bl0[4], bl1[4];
#pragma unroll
            for (int nt = 0; nt < 4; ++nt) {
                bh0[nt] = xh0[nt * 8]; bh1[nt] = xh1[nt * 8];
                bl0[nt] = xl0[nt * 8]; bl1[nt] = xl1[nt * 8];
            }
#pragma unroll
            for (int nt = 0; nt < 4; ++nt) {
                mma16816(a2[nt], Ah, bh0[nt], bh1[nt]);
                mma16816(a2[nt], Ah, bl0[nt], bl1[nt]);
                mma16816(a2[nt], Al, bh0[nt], bh1[nt]);
            }
        }
        if (RELU2) {
#pragma unroll
            for (int nt = 0; nt < 4; ++nt)
#pragma unroll
                for (int j = 0; j < 4; ++j) a2[nt][j] = fmaxf(a2[nt][j], 0.0f);
        }
        __syncthreads();   // sS reuse safe
        float sA = 0.0f, sB = 0.0f;
#pragma unroll
        for (int nt = 0; nt < 4; ++nt) { sA += a2[nt][0] + a2[nt][1]; sB += a2[nt][2] + a2[nt][3]; }
        sA += __shfl_xor_sync(0xffffffffu, sA, 1); sA += __shfl_xor_sync(0xffffffffu, sA, 2);
        sB += __shfl_xor_sync(0xffffffffu, sB, 1); sB += __shfl_xor_sync(0xffffffffu, sB, 2);
        if (q == 0) { sS[h2 * 80 + o_r] = sA; sS[h2 * 80 + o_r8] = sB; }
        __syncthreads();
        float SA = sS[o_r] + sS[80 + o_r];
        float SB = sS[o_r8] + sS[80 + o_r8];

        float* gout = (RELU2 ? g_r : g_msgs) + (size_t)ba * 4096;
#pragma unroll
        for (int nt = 0; nt < 4; ++nt) {
            int u0 = ub + nt * 8 + q * 2;
            float2 vA, vB;
            if (s >= 2) {
                vA.x = (SA - a2[nt][0]) * inv; vA.y = (SA - a2[nt][1]) * inv;
                vB.x = (SB - a2[nt][2]) * inv; vB.y = (SB - a2[nt][3]) * inv;
            } else {
                vA.x = a2[nt][0]; vA.y = a2[nt][1];
                vB.x = a2[nt][2]; vB.y = a2[nt][3];
            }
            *reinterpret_cast<float2*>(gout + o_r * 64 + u0)  = vA;
            *reinterpret_cast<float2*>(gout + o_r8 * 64 + u0) = vB;
        }
    } else {
        // final conv2: 1x64 GEMV over sH
        const int u = t >> 2, part = t & 3;
        float sv = 0.0f;
        const int c0 = part * 16;
#pragma unroll
        for (int c = c0; c < c0 + 16; ++c)
            sv = fmaf(__ldg(w2raw + c), sH[c * 66 + u], sv);
        sv += __shfl_xor_sync(0xffffffffu, sv, 1);
        sv += __shfl_xor_sync(0xffffffffu, sv, 2);
        if (part == 0) {
            const int a = ba & 63;
            dout[b * 4096 + u * 64 + a] = sv + __ldg(b2v);
        }
    }
}

// ---------------- launch -----------------------------------------------------
extern "C" void kernel_launch(void* const* d_in, const int* in_sizes, int n_in,
                              void* d_out, int out_size) {
    (void)in_sizes; (void)n_in; (void)out_size;
    const float* cg      = (const float*)d_in[0];
    const float* phi1_W1 = (const float*)d_in[1];
    const float* phi1_b1 = (const float*)d_in[2];
    const float* phi1_W2 = (const float*)d_in[3];
    const float* phi1_b2 = (const float*)d_in[4];
    const float* phiK_W1 = (const float*)d_in[5];
    const float* phiK_b1 = (const float*)d_in[6];
    const float* phiK_W2 = (const float*)d_in[7];
    const float* phiK_b2 = (const float*)d_in[8];
    const float* g1_W1   = (const float*)d_in[9];
    const float* g1_b1   = (const float*)d_in[10];
    const float* g1_W2   = (const float*)d_in[11];
    const float* g1_b2   = (const float*)d_in[12];
    const float* gK_W1   = (const float*)d_in[13];
    const float* gK_b1   = (const float*)d_in[14];
    const float* gK_W2   = (const float*)d_in[15];
    const float* gK_b2   = (const float*)d_in[16];
    const float* g5_W1   = (const float*)d_in[17];
    const float* g5_b1   = (const float*)d_in[18];
    const float* g5_W2   = (const float*)d_in[19];
    const float* g5_b2   = (const float*)d_in[20];
    float* out = (float*)d_out;

    // smem bytes: (KB1*1024 + 4096 + 2*XR*72)*4 + 64*66*4 + 160*4
    auto smem_bytes = [](int KB1) {
        int XR = (KB1 * 8 < 32) ? 32 : KB1 * 8;
        return (KB1 * 1024 + 4096 + 2 * XR * 72) * 4 + 64 * 66 * 4 + 160 * 4;
    };
    const int SM1 = smem_bytes(1);
    const int SM5 = smem_bytes(5);
    const int SM8 = smem_bytes(8);

    cudaFuncSetAttribute(layer_kernel<1, 0, false, false>, cudaFuncAttributeMaxDynamicSharedMemorySize, SM1);
    cudaFuncSetAttribute(layer_kernel<5, 1, false, false>, cudaFuncAttributeMaxDynamicSharedMemorySize, SM5);
    cudaFuncSetAttribute(layer_kernel<5, 2, true,  false>, cudaFuncAttributeMaxDynamicSharedMemorySize, SM5);
    cudaFuncSetAttribute(layer_kernel<8, 3, true,  false>, cudaFuncAttributeMaxDynamicSharedMemorySize, SM8);
    cudaFuncSetAttribute(layer_kernel<8, 3, true,  true>,  cudaFuncAttributeMaxDynamicSharedMemorySize, SM8);

    prep_kernel<<<19, 256>>>(phi1_W1, phi1_W2, phiK_W1, phiK_W2, g1_W1, g1_W2, gK_W1, gK_W2, g5_W1);
    cgt_kernel<<<128, 256>>>(cg);

    layer_kernel<1, 0, false, false><<<NBA, 256, SM1>>>(phi1_b1, phi1_b2, OFF_PHI1_W1F, OFF_PHI1_W2F, nullptr, nullptr);
    asum_kernel<<<2048, 256>>>();
    layer_kernel<5, 2, true, false><<<NBA, 256, SM5>>>(g1_b1, g1_b2, OFF_G1_W1F, OFF_G1_W2F, nullptr, nullptr);

    for (int i = 0; i < 4; ++i) {
        layer_kernel<5, 1, false, false><<<NBA, 256, SM5>>>(phiK_b1 + i * 64, phiK_b2 + i * 64,
                                                            OFF_PHIK_W1F + i * 5120, OFF_PHIK_W2F + i * 4096,
                                                            nullptr, nullptr);
        asum_kernel<<<2048, 256>>>();
        if (i < 3) {
            layer_kernel<8, 3, true, false><<<NBA, 256, SM8>>>(gK_b1 + i * 64, gK_b2 + i * 64,
                                                               OFF_GK_W1F + i * 8192, OFF_GK_W2F + i * 4096,
                                                               nullptr, nullptr);
        } else {
            layer_kernel<8, 3, true, true><<<NBA, 256, SM8>>>(g5_b1, g5_b2,
                                                              OFF_G5_W1F, 0, g5_W2, out);
        }
    }
}

// round 6
// speedup vs baseline: 1.9186x; 1.6098x over previous
#include <cuda_runtime.h>
#include <cuda_bf16.h>
#include <cstdint>

// B=128, U=64, A=64. GEMMs: bf16 mma.sync m16n8k16, 3-term hi/lo emulation.
// Intermediates stored PACKED bf16 hi/lo: slice = [plane(2)][pair_c(32)][u(64)] u32.
// Persistent CTAs; gamma agg S-term precomputed per-b (pP kernel).

#define NBA 8192

__device__ __align__(16) uint32_t g_cgPh[NBA * 64];
__device__ __align__(16) uint32_t g_cgPl[NBA * 64];
__device__ __align__(16) uint32_t g_rP[(size_t)NBA * 4096];
__device__ __align__(16) uint32_t g_msgsP[(size_t)NBA * 4096];
__device__ float g_sums[128 * 4096];                   // [b][c][u]
__device__ float g_P[128 * 4096];                      // [b][o][u] (bias1 + Wagg*S/63)
__device__ __align__(16) uint32_t g_wfrag[96256];

#define OFF_PHI1_W1F 0
#define OFF_PHI1_W2F 1024
#define OFF_PHIK_W1F 5120
#define OFF_PHIK_W2F 25600
#define OFF_G1_W1F   41984
#define OFF_G1_W2F   47104
#define OFF_GK_W1F   51200
#define OFF_GK_W2F   75776
#define OFF_G5_W1F   88064

__device__ __forceinline__ uint32_t pack2(float a, float b) {
    uint32_t la = (uint32_t)__bfloat16_as_ushort(__float2bfloat16_rn(a));
    uint32_t lb = (uint32_t)__bfloat16_as_ushort(__float2bfloat16_rn(b));
    return la | (lb << 16);
}
__device__ __forceinline__ void split1(float v, float& hi, float& lo) {
    hi = __bfloat162float(__float2bfloat16_rn(v));
    lo = v - hi;
}
__device__ __forceinline__ void mma16816(float d[4], const uint4& a, uint32_t b0, uint32_t b1) {
    asm volatile("mma.sync.aligned.m16n8k16.row.col.f32.bf16.bf16.f32 "
                 "{%0,%1,%2,%3}, {%4,%5,%6,%7}, {%8,%9}, {%0,%1,%2,%3};\n"
                 : "+f"(d[0]), "+f"(d[1]), "+f"(d[2]), "+f"(d[3])
                 : "r"(a.x), "r"(a.y), "r"(a.z), "r"(a.w), "r"(b0), "r"(b1));
}

// ---------------- prep: bf16 hi/lo A-fragments -------------------------------
// types: 0 C=64; 1 C=65 (cg col0 -> c64);  3 folded phi1;
//        4 gamma1 (C=65, agg cols scaled -1/63, cg->c64); 5 gammaK (C=128, cols64+ scaled -1/63)
__global__ void prep_kernel(const float* __restrict__ phi1W1, const float* __restrict__ phi1W2,
                            const float* __restrict__ phiKW1, const float* __restrict__ phiKW2,
                            const float* __restrict__ g1W1,   const float* __restrict__ g1W2,
                            const float* __restrict__ gKW1,   const float* __restrict__ gKW2,
                            const float* __restrict__ g5W1) {
    const int id = blockIdx.x;
    const float* src; int off, KB, type;
    if (id == 0)       { src = phi1W1;              off = OFF_PHI1_W1F;            KB = 1; type = 3; }
    else if (id == 1)  { src = phi1W2;              off = OFF_PHI1_W2F;            KB = 4; type = 0; }
    else if (id < 6)   { int i = id - 2;  src = phiKW1 + i * 64 * 65;  off = OFF_PHIK_W1F + i * 5120; KB = 5; type = 1; }
    else if (id < 10)  { int i = id - 6;  src = phiKW2 + i * 4096;     off = OFF_PHIK_W2F + i * 4096; KB = 4; type = 0; }
    else if (id == 10) { src = g1W1;                off = OFF_G1_W1F;              KB = 5; type = 4; }
    else if (id == 11) { src = g1W2;                off = OFF_G1_W2F;              KB = 4; type = 0; }
    else if (id < 15)  { int i = id - 12; src = gKW1 + i * 64 * 128;   off = OFF_GK_W1F + i * 8192;   KB = 8; type = 5; }
    else if (id < 18)  { int i = id - 15; src = gKW2 + i * 4096;       off = OFF_GK_W2F + i * 4096;   KB = 4; type = 0; }
    else               { src = g5W1;                off = OFF_G5_W1F;              KB = 8; type = 5; }

    const float ninv = -1.0f / 63.0f;
    const int total = KB * 1024;
    for (int e = threadIdx.x; e < total; e += blockDim.x) {
        int strip = e / (KB * 256);
        int rem   = e % (KB * 256);
        int kt = rem / 256;
        int r2 = rem % 256;
        int plane = r2 >> 7;
        int r3 = r2 & 127;
        int lane = r3 >> 2, j = r3 & 3;
        int o  = strip * 16 + (lane >> 2) + 8 * (j & 1);
        int k0 = kt * 16 + (lane & 3) * 2 + 8 * (j >> 1);
        float w0, w1;
        if (type == 0)      { w0 = src[o * 64 + k0];  w1 = src[o * 64 + k0 + 1]; }
        else if (type == 5) { w0 = src[o * 128 + k0]; w1 = src[o * 128 + k0 + 1];
                              if (k0 >= 64) { w0 *= ninv; w1 *= ninv; } }
        else if (type == 1 || type == 4) {
            auto fetch = [&](int c) -> float {
                if (c < 64) {
                    float v = src[o * 65 + 1 + c];
                    return (type == 4) ? v * ninv : v;
                }
                if (c == 64) return src[o * 65];
                return 0.0f;
            };
            w0 = fetch(k0); w1 = fetch(k0 + 1);
        } else {
            w0 = (k0 == 0) ? (src[o * 2] + src[o * 2 + 1]) : 0.0f;
            w1 = 0.0f;
        }
        float h0, l0, h1, l1; split1(w0, h0, l0); split1(w1, h1, l1);
        g_wfrag[off + e] = plane ? pack2(l0, l1) : pack2(h0, h1);
    }
}

// ---------------- cg transpose + pack ----------------------------------------
__global__ void cgt_kernel(const float* __restrict__ cg) {
    const int b = blockIdx.x;
    for (int j = threadIdx.x; j < 4096; j += 256) {
        int a = j >> 6, u = j & 63;
        float v = cg[b * 4096 + u * 64 + a];
        uint32_t bits = __float_as_uint(v);
        float lo = v - __uint_as_float(bits & 0xffff0000u);
        g_cgPh[(b * 64 + a) * 64 + u] = bits >> 16;
        g_cgPl[(b * 64 + a) * 64 + u] = (uint32_t)__bfloat16_as_ushort(__float2bfloat16_rn(lo));
    }
}

// ---------------- sum over a of packed msgs -----------------------------------
__global__ void asum_kernel() {
    const int b = blockIdx.x >> 3;
    const int e = (blockIdx.x & 7) * 256 + threadIdx.x;   // pair*64+u
    const uint32_t* p0 = g_msgsP + (size_t)b * 262144 + e;
    float s0 = 0.f, s1 = 0.f;
#pragma unroll 4
    for (int a = 0; a < 64; ++a) {
        uint32_t h = p0[(size_t)a * 4096];
        uint32_t l = p0[(size_t)a * 4096 + 2048];
        s0 += __uint_as_float(h << 16) + __uint_as_float(l << 16);
        s1 += __uint_as_float(h & 0xffff0000u) + __uint_as_float(l & 0xffff0000u);
    }
    int pr = e >> 6, u = e & 63;
    g_sums[b * 4096 + (2 * pr) * 64 + u]     = s0;
    g_sums[b * 4096 + (2 * pr + 1) * 64 + u] = s1;
}

// ---------------- per-b precompute: P = bias1 + (Wagg/63)*S -------------------
__global__ void pP_kernel(const float* __restrict__ Wsrc, const float* __restrict__ b1,
                          int CW, int cOff) {
    __shared__ float sWT[64 * 65];
    __shared__ float sS2[4096];
    const int b = blockIdx.x, t = threadIdx.x;
    for (int idx = t; idx < 4096; idx += 256) {
        int o = idx >> 6, c = idx & 63;
        sWT[c * 65 + o] = Wsrc[o * CW + cOff + c] * (1.0f / 63.0f);
        sS2[idx] = g_sums[b * 4096 + idx];
    }
    __syncthreads();
    const int o = t & 63, ublk = t >> 6;
    float acc[16];
    float bv = __ldg(b1 + o);
#pragma unroll
    for (int i = 0; i < 16; ++i) acc[i] = bv;
    const float4* S4 = (const float4*)sS2;
#pragma unroll 4
    for (int c = 0; c < 64; ++c) {
        float w = sWT[c * 65 + o];
#pragma unroll
        for (int i = 0; i < 4; ++i) {
            float4 s = S4[c * 16 + ublk * 4 + i];
            acc[i * 4 + 0] += w * s.x; acc[i * 4 + 1] += w * s.y;
            acc[i * 4 + 2] += w * s.z; acc[i * 4 + 3] += w * s.w;
        }
    }
    float4* P4 = (float4*)(g_P + b * 4096 + o * 64 + ublk * 16);
#pragma unroll
    for (int i = 0; i < 4; ++i)
        P4[i] = make_float4(acc[i * 4], acc[i * 4 + 1], acc[i * 4 + 2], acc[i * 4 + 3]);
}

// ---------------- layer kernel (persistent) -----------------------------------
// MODE: 0 phi1, 1 phiK, 2 gamma1, 3 gammaK/gamma5
template<int KB1, int MODE, bool FINAL>
__global__ void __launch_bounds__(256) layer_kernel(const float* __restrict__ b1v,
                                                    const float* __restrict__ b2v,
                                                    int w1off, int w2off,
                                                    const float* __restrict__ w2raw,
                                                    float* __restrict__ dout) {
    constexpr bool RELU2 = (MODE >= 2);
    constexpr int XR = (KB1 * 8 < 32) ? 32 : KB1 * 8;
    extern __shared__ uint32_t sm[];
    uint32_t* sW1f = sm;                                  // KB1*1024
    uint32_t* sW2f = sW1f + KB1 * 1024;                   // 4096 (absent for FINAL)
    uint32_t* sXh  = sW2f + (FINAL ? 0 : 4096);           // XR*72
    uint32_t* sXl  = sXh + XR * 72;                       // XR*72
    float*    sS   = (float*)(sXl + XR * 72);             // 160
    float*    sH   = sS + 160;                            // 64*66 (FINAL only)

    const int t = threadIdx.x;
    const int warp = t >> 5, lane = t & 31, q = lane & 3, g = lane >> 2;
    const int s = warp >> 1, h2 = warp & 1;
    const int ub = h2 * 32;
    const int o_r = s * 16 + g, o_r8 = o_r + 8;
    const bool geven = ((g & 1) == 0);
    const float inv = 1.0f / 63.0f;

    // weights once per CTA
    {
        const uint4* gw1 = (const uint4*)(g_wfrag + w1off);
        uint4* d1 = (uint4*)sW1f;
        for (int i = t; i < KB1 * 256; i += 256) d1[i] = gw1[i];
        if (!FINAL) {
            const uint4* gw2 = (const uint4*)(g_wfrag + w2off);
            uint4* d2 = (uint4*)sW2f;
#pragma unroll
            for (int k = 0; k < 4; ++k) d2[t + k * 256] = gw2[t + k * 256];
        }
    }
    float bA1 = 0.f, bB1 = 0.f, bA2 = 0.f, bB2 = 0.f;
    if (MODE < 2) { bA1 = __ldg(b1v + o_r); bB1 = __ldg(b1v + o_r8); }
    if (!FINAL)   { bA2 = __ldg(b2v + o_r); bB2 = __ldg(b2v + o_r8); }
    __syncthreads();

    for (int ba = blockIdx.x; ba < NBA; ba += gridDim.x) {
        const int b = ba >> 6;
        const uint32_t* rP = g_rP + (size_t)ba * 4096;
        const uint32_t* mP = g_msgsP + (size_t)ba * 4096;
        const uint32_t* ch = g_cgPh + ba * 64;
        const uint32_t* cl = g_cgPl + ba * 64;

        // ---- pack X: pure copies ----
        for (int idx = t; idx < XR * 64; idx += 256) {
            int row = idx >> 6, u = idx & 63;
            uint32_t h = 0, l = 0;
            if (MODE == 0) {
                if (row == 0) { h = ch[u]; l = cl[u]; }
            } else if (MODE == 1) {
                if (row < 32) { h = rP[idx]; l = rP[2048 + idx]; }
                else if (row == 32) { h = ch[u]; l = cl[u]; }
            } else if (MODE == 2) {
                if (row < 32) { h = mP[idx]; l = mP[2048 + idx]; }
                else if (row == 32) { h = ch[u]; l = cl[u]; }
            } else {
                if (row < 32) { h = rP[idx]; l = rP[2048 + idx]; }
                else { h = mP[idx - 2048]; l = mP[idx]; }
            }
            sXh[row * 72 + u] = h; sXl[row * 72 + u] = l;
        }
        __syncthreads();

        // ---- conv1 ----
        float acc[4][4];
        if (MODE >= 2) {
            const float* Pb = g_P + b * 4096;
#pragma unroll
            for (int nt = 0; nt < 4; ++nt) {
                int u0 = ub + nt * 8 + q * 2;
                float2 pa = __ldg((const float2*)(Pb + o_r * 64 + u0));
                float2 pb = __ldg((const float2*)(Pb + o_r8 * 64 + u0));
                acc[nt][0] = pa.x; acc[nt][1] = pa.y; acc[nt][2] = pb.x; acc[nt][3] = pb.y;
            }
        } else {
#pragma unroll
            for (int nt = 0; nt < 4; ++nt) { acc[nt][0] = bA1; acc[nt][1] = bA1; acc[nt][2] = bB1; acc[nt][3] = bB1; }
        }
        {
            const uint4* A1 = (const uint4*)sW1f + s * (KB1 * 64);
#pragma unroll
            for (int kt = 0; kt < KB1; ++kt) {
                uint4 Ah = A1[kt * 64 + lane];
                uint4 Al = A1[kt * 64 + 32 + lane];
                const uint32_t* xh0 = sXh + (kt * 8 + q) * 72 + ub + g;
                const uint32_t* xh1 = sXh + (kt * 8 + 4 + q) * 72 + ub + g;
                const uint32_t* xl0 = sXl + (kt * 8 + q) * 72 + ub + g;
                const uint32_t* xl1 = sXl + (kt * 8 + 4 + q) * 72 + ub + g;
                uint32_t bh0[4], bh1[4], bl0[4], bl1[4];
#pragma unroll
                for (int nt = 0; nt < 4; ++nt) {
                    bh0[nt] = xh0[nt * 8]; bh1[nt] = xh1[nt * 8];
                    bl0[nt] = xl0[nt * 8]; bl1[nt] = xl1[nt * 8];
                }
#pragma unroll
                for (int nt = 0; nt < 4; ++nt) {
                    mma16816(acc[nt], Ah, bh0[nt], bh1[nt]);
                    mma16816(acc[nt], Ah, bl0[nt], bl1[nt]);
                    mma16816(acc[nt], Al, bh0[nt], bh1[nt]);
                }
            }
        }
        // relu + colsum
#pragma unroll
        for (int nt = 0; nt < 4; ++nt)
#pragma unroll
            for (int j = 0; j < 4; ++j) acc[nt][j] = fmaxf(acc[nt][j], 0.0f);
        {
            float sA = 0.f, sB = 0.f;
#pragma unroll
            for (int nt = 0; nt < 4; ++nt) { sA += acc[nt][0] + acc[nt][1]; sB += acc[nt][2] + acc[nt][3]; }
            sA += __shfl_xor_sync(0xffffffffu, sA, 1); sA += __shfl_xor_sync(0xffffffffu, sA, 2);
            sB += __shfl_xor_sync(0xffffffffu, sB, 1); sB += __shfl_xor_sync(0xffffffffu, sB, 2);
            if (q == 0) { sS[h2 * 80 + o_r] = sA; sS[h2 * 80 + o_r8] = sB; }
        }
        __syncthreads();
        float SA = sS[o_r] + sS[80 + o_r];
        float SB = sS[o_r8] + sS[80 + o_r8];

        if (!FINAL) {
            // post + pair-pack directly into sXh/sXl rows 0..31
#pragma unroll
            for (int nt = 0; nt < 4; ++nt) {
                float t0, t1, t2, t3;
                if (s >= 2) {
                    t0 = (SA - acc[nt][0]) * inv; t1 = (SA - acc[nt][1]) * inv;
                    t2 = (SB - acc[nt][2]) * inv; t3 = (SB - acc[nt][3]) * inv;
                } else { t0 = acc[nt][0]; t1 = acc[nt][1]; t2 = acc[nt][2]; t3 = acc[nt][3]; }
                float p0 = __shfl_xor_sync(0xffffffffu, t0, 4);
                float p1 = __shfl_xor_sync(0xffffffffu, t1, 4);
                float p2 = __shfl_xor_sync(0xffffffffu, t2, 4);
                float p3 = __shfl_xor_sync(0xffffffffu, t3, 4);
                float v0a, v0b, v1a, v1b; int c2;
                if (geven) { c2 = (s * 16 + g) >> 1;          v0a = t0; v0b = p0; v1a = t1; v1b = p1; }
                else       { c2 = (s * 16 + 8 + g - 1) >> 1;  v0a = p2; v0b = t2; v1a = p3; v1b = t3; }
                uint32_t ba0 = __float_as_uint(v0a), bb0 = __float_as_uint(v0b);
                uint32_t ba1 = __float_as_uint(v1a), bb1 = __float_as_uint(v1b);
                uint32_t ph0 = __byte_perm(ba0, bb0, 0x7632);
                uint32_t ph1 = __byte_perm(ba1, bb1, 0x7632);
                float l0a = v0a - __uint_as_float(ba0 & 0xffff0000u);
                float l0b = v0b - __uint_as_float(bb0 & 0xffff0000u);
                float l1a = v1a - __uint_as_float(ba1 & 0xffff0000u);
                float l1b = v1b - __uint_as_float(bb1 & 0xffff0000u);
                uint32_t pl0 = pack2(l0a, l0b);
                uint32_t pl1 = pack2(l1a, l1b);
                int u0 = ub + nt * 8 + q * 2;
                sXh[c2 * 72 + u0] = ph0; sXh[c2 * 72 + u0 + 1] = ph1;
                sXl[c2 * 72 + u0] = pl0; sXl[c2 * 72 + u0 + 1] = pl1;
            }
            __syncthreads();

            // ---- conv2 (KB=4) ----
            float a2[4][4];
#pragma unroll
            for (int nt = 0; nt < 4; ++nt) { a2[nt][0] = bA2; a2[nt][1] = bA2; a2[nt][2] = bB2; a2[nt][3] = bB2; }
            const uint4* A2 = (const uint4*)sW2f + s * 256;
#pragma unroll
            for (int kt = 0; kt < 4; ++kt) {
                uint4 Ah = A2[kt * 64 + lane];
                uint4 Al = A2[kt * 64 + 32 + lane];
                const uint32_t* xh0 = sXh + (kt * 8 + q) * 72 + ub + g;
                const uint32_t* xh1 = sXh + (kt * 8 + 4 + q) * 72 + ub + g;
                const uint32_t* xl0 = sXl + (kt * 8 + q) * 72 + ub + g;
                const uint32_t* xl1 = sXl + (kt * 8 + 4 + q) * 72 + ub + g;
                uint32_t bh0[4], bh1[4], bl0[4], bl1[4];
#pragma unroll
                for (int nt = 0; nt < 4; ++nt) {
                    bh0[nt] = xh0[nt * 8]; bh1[nt] = xh1[nt * 8];
                    bl0[nt] = xl0[nt * 8]; bl1[nt] = xl1[nt * 8];
                }
#pragma unroll
                for (int nt = 0; nt < 4; ++nt) {
                    mma16816(a2[nt], Ah, bh0[nt], bh1[nt]);
                    mma16816(a2[nt], Ah, bl0[nt], bl1[nt]);
                    mma16816(a2[nt], Al, bh0[nt], bh1[nt]);
                }
            }
            if (RELU2) {
#pragma unroll
                for (int nt = 0; nt < 4; ++nt)
#pragma unroll
                    for (int j = 0; j < 4; ++j) a2[nt][j] = fmaxf(a2[nt][j], 0.0f);
            }
            float s2A = 0.f, s2B = 0.f;
#pragma unroll
            for (int nt = 0; nt < 4; ++nt) { s2A += a2[nt][0] + a2[nt][1]; s2B += a2[nt][2] + a2[nt][3]; }
            s2A += __shfl_xor_sync(0xffffffffu, s2A, 1); s2A += __shfl_xor_sync(0xffffffffu, s2A, 2);
            s2B += __shfl_xor_sync(0xffffffffu, s2B, 1); s2B += __shfl_xor_sync(0xffffffffu, s2B, 2);
            if (q == 0) { sS[h2 * 80 + o_r] = s2A; sS[h2 * 80 + o_r8] = s2B; }
            __syncthreads();
            float S2A = sS[o_r] + sS[80 + o_r];
            float S2B = sS[o_r8] + sS[80 + o_r8];

            uint32_t* gout = (RELU2 ? g_rP : g_msgsP) + (size_t)ba * 4096;
#pragma unroll
            for (int nt = 0; nt < 4; ++nt) {
                float t0, t1, t2, t3;
                if (s >= 2) {
                    t0 = (S2A - a2[nt][0]) * inv; t1 = (S2A - a2[nt][1]) * inv;
                    t2 = (S2B - a2[nt][2]) * inv; t3 = (S2B - a2[nt][3]) * inv;
                } else { t0 = a2[nt][0]; t1 = a2[nt][1]; t2 = a2[nt][2]; t3 = a2[nt][3]; }
                float p0 = __shfl_xor_sync(0xffffffffu, t0, 4);
                float p1 = __shfl_xor_sync(0xffffffffu, t1, 4);
                float p2 = __shfl_xor_sync(0xffffffffu, t2, 4);
                float p3 = __shfl_xor_sync(0xffffffffu, t3, 4);
                float v0a, v0b, v1a, v1b; int c2;
                if (geven) { c2 = (s * 16 + g) >> 1;          v0a = t0; v0b = p0; v1a = t1; v1b = p1; }
                else       { c2 = (s * 16 + 8 + g - 1) >> 1;  v0a = p2; v0b = t2; v1a = p3; v1b = t3; }
                uint32_t ba0 = __float_as_uint(v0a), bb0 = __float_as_uint(v0b);
                uint32_t ba1 = __float_as_uint(v1a), bb1 = __float_as_uint(v1b);
                uint32_t ph0 = __byte_perm(ba0, bb0, 0x7632);
                uint32_t ph1 = __byte_perm(ba1, bb1, 0x7632);
                float l0a = v0a - __uint_as_float(ba0 & 0xffff0000u);
                float l0b = v0b - __uint_as_float(bb0 & 0xffff0000u);
                float l1a = v1a - __uint_as_float(ba1 & 0xffff0000u);
                float l1b = v1b - __uint_as_float(bb1 & 0xffff0000u);
                uint32_t pl0 = pack2(l0a, l0b);
                uint32_t pl1 = pack2(l1a, l1b);
                int u0 = ub + nt * 8 + q * 2;
                uint2 vh; vh.x = ph0; vh.y = ph1;
                uint2 vl; vl.x = pl0; vl.y = pl1;
                *(uint2*)(gout + c2 * 64 + u0) = vh;
                *(uint2*)(gout + 2048 + c2 * 64 + u0) = vl;
            }
        } else {
            // FINAL: write post-transformed H to sH (fp32), then 1x64 GEMV
#pragma unroll
            for (int nt = 0; nt < 4; ++nt) {
                int u0 = ub + nt * 8 + q * 2;
                float2 vA, vB;
                if (s >= 2) {
                    vA.x = (SA - acc[nt][0]) * inv; vA.y = (SA - acc[nt][1]) * inv;
                    vB.x = (SB - acc[nt][2]) * inv; vB.y = (SB - acc[nt][3]) * inv;
                } else { vA.x = acc[nt][0]; vA.y = acc[nt][1]; vB.x = acc[nt][2]; vB.y = acc[nt][3]; }
                *(float2*)(sH + o_r * 66 + u0)  = vA;
                *(float2*)(sH + o_r8 * 66 + u0) = vB;
            }
            __syncthreads();
            const int u = t >> 2, part = t & 3;
            float sv = 0.0f;
            const int c0 = part * 16;
#pragma unroll
            for (int c = c0; c < c0 + 16; ++c)
                sv = fmaf(__ldg(w2raw + c), sH[c * 66 + u], sv);
            sv += __shfl_xor_sync(0xffffffffu, sv, 1);
            sv += __shfl_xor_sync(0xffffffffu, sv, 2);
            if (part == 0)
                dout[b * 4096 + u * 64 + (ba & 63)] = sv + __ldg(b2v);
            __syncthreads();
        }
    }
}

// ---------------- launch -----------------------------------------------------
extern "C" void kernel_launch(void* const* d_in, const int* in_sizes, int n_in,
                              void* d_out, int out_size) {
    (void)in_sizes; (void)n_in; (void)out_size;
    const float* cg      = (const float*)d_in[0];
    const float* phi1_W1 = (const float*)d_in[1];
    const float* phi1_b1 = (const float*)d_in[2];
    const float* phi1_W2 = (const float*)d_in[3];
    const float* phi1_b2 = (const float*)d_in[4];
    const float* phiK_W1 = (const float*)d_in[5];
    const float* phiK_b1 = (const float*)d_in[6];
    const float* phiK_W2 = (const float*)d_in[7];
    const float* phiK_b2 = (const float*)d_in[8];
    const float* g1_W1   = (const float*)d_in[9];
    const float* g1_b1   = (const float*)d_in[10];
    const float* g1_W2   = (const float*)d_in[11];
    const float* g1_b2   = (const float*)d_in[12];
    const float* gK_W1   = (const float*)d_in[13];
    const float* gK_b1   = (const float*)d_in[14];
    const float* gK_W2   = (const float*)d_in[15];
    const float* gK_b2   = (const float*)d_in[16];
    const float* g5_W1   = (const float*)d_in[17];
    const float* g5_b1   = (const float*)d_in[18];
    const float* g5_W2   = (const float*)d_in[19];
    const float* g5_b2   = (const float*)d_in[20];
    float* out = (float*)d_out;

    auto smem_bytes = [](int KB1, bool fin) {
        int XR = (KB1 * 8 < 32) ? 32 : KB1 * 8;
        int u32s = KB1 * 1024 + (fin ? 0 : 4096) + 2 * XR * 72 + 160 + (fin ? 64 * 66 : 0);
        return u32s * 4;
    };
    const int SM1 = smem_bytes(1, false);
    const int SM5 = smem_bytes(5, false);
    const int SM8 = smem_bytes(8, false);
    const int SMF = smem_bytes(8, true);

    cudaFuncSetAttribute(layer_kernel<1, 0, false>, cudaFuncAttributeMaxDynamicSharedMemorySize, SM1);
    cudaFuncSetAttribute(layer_kernel<5, 1, false>, cudaFuncAttributeMaxDynamicSharedMemorySize, SM5);
    cudaFuncSetAttribute(layer_kernel<5, 2, false>, cudaFuncAttributeMaxDynamicSharedMemorySize, SM5);
    cudaFuncSetAttribute(layer_kernel<8, 3, false>, cudaFuncAttributeMaxDynamicSharedMemorySize, SM8);
    cudaFuncSetAttribute(layer_kernel<8, 3, true>,  cudaFuncAttributeMaxDynamicSharedMemorySize, SMF);

    prep_kernel<<<19, 256>>>(phi1_W1, phi1_W2, phiK_W1, phiK_W2, g1_W1, g1_W2, gK_W1, gK_W2, g5_W1);
    cgt_kernel<<<128, 256>>>(cg);

    const int G5 = 444, G8 = 296, G1 = 592;

    layer_kernel<1, 0, false><<<G1, 256, SM1>>>(phi1_b1, phi1_b2, OFF_PHI1_W1F, OFF_PHI1_W2F, nullptr, nullptr);
    asum_kernel<<<1024, 256>>>();
    pP_kernel<<<128, 256>>>(g1_W1, g1_b1, 65, 1);
    layer_kernel<5, 2, false><<<G5, 256, SM5>>>(nullptr, g1_b2, OFF_G1_W1F, OFF_G1_W2F, nullptr, nullptr);

    for (int i = 0; i < 4; ++i) {
        layer_kernel<5, 1, false><<<G5, 256, SM5>>>(phiK_b1 + i * 64, phiK_b2 + i * 64,
                                                    OFF_PHIK_W1F + i * 5120, OFF_PHIK_W2F + i * 4096,
                                                    nullptr, nullptr);
        asum_kernel<<<1024, 256>>>();
        if (i < 3) {
            pP_kernel<<<128, 256>>>(gK_W1 + i * 8192, gK_b1 + i * 64, 128, 64);
            layer_kernel<8, 3, false><<<G8, 256, SM8>>>(nullptr, gK_b2 + i * 64,
                                                        OFF_GK_W1F + i * 8192, OFF_GK_W2F + i * 4096,
                                                        nullptr, nullptr);
        } else {
            pP_kernel<<<128, 256>>>(g5_W1, g5_b1, 128, 64);
            layer_kernel<8, 3, true><<<G8, 256, SMF>>>(nullptr, g5_b2,
                                                       OFF_G5_W1F, 0, g5_W2, out);
        }
    }
}

// round 7
// speedup vs baseline: 2.5590x; 1.3338x over previous
#include <cuda_runtime.h>
#include <cuda_bf16.h>
#include <cstdint>

// B=128, U=64, A=64. GEMMs: bf16 mma.sync m16n8k16, 3-term hi/lo emulation.
// Intermediates PACKED bf16 hi/lo: slice = [plane(2)][pair_c(32)][u(64)] u32.
// Persistent CTAs + cp.async double-buffered X; W2 fragments in registers.

#define NBA 8192

__device__ __align__(16) uint32_t g_cgPh[NBA * 64];
__device__ __align__(16) uint32_t g_cgPl[NBA * 64];
__device__ __align__(16) uint32_t g_rP[(size_t)NBA * 4096];
__device__ __align__(16) uint32_t g_msgsP[(size_t)NBA * 4096];
__device__ float g_sums[128 * 4096];
__device__ float g_P[128 * 4096];
__device__ __align__(16) uint32_t g_wfrag[96256];

#define OFF_PHI1_W1F 0
#define OFF_PHI1_W2F 1024
#define OFF_PHIK_W1F 5120
#define OFF_PHIK_W2F 25600
#define OFF_G1_W1F   41984
#define OFF_G1_W2F   47104
#define OFF_GK_W1F   51200
#define OFF_GK_W2F   75776
#define OFF_G5_W1F   88064

#define CP_ASYNC16(dst, src) asm volatile("cp.async.cg.shared.global [%0], [%1], 16;" :: "r"(dst), "l"(src))
#define CP_COMMIT()          asm volatile("cp.async.commit_group;" ::: "memory")
#define CP_WAIT1()           asm volatile("cp.async.wait_group 1;" ::: "memory")
#define CP_WAIT0()           asm volatile("cp.async.wait_group 0;" ::: "memory")

__device__ __forceinline__ uint32_t pack2(float a, float b) {
    uint32_t la = (uint32_t)__bfloat16_as_ushort(__float2bfloat16_rn(a));
    uint32_t lb = (uint32_t)__bfloat16_as_ushort(__float2bfloat16_rn(b));
    return la | (lb << 16);
}
__device__ __forceinline__ void split1(float v, float& hi, float& lo) {
    hi = __bfloat162float(__float2bfloat16_rn(v));
    lo = v - hi;
}
__device__ __forceinline__ void mma16816(float d[4], const uint4& a, uint32_t b0, uint32_t b1) {
    asm volatile("mma.sync.aligned.m16n8k16.row.col.f32.bf16.bf16.f32 "
                 "{%0,%1,%2,%3}, {%4,%5,%6,%7}, {%8,%9}, {%0,%1,%2,%3};\n"
                 : "+f"(d[0]), "+f"(d[1]), "+f"(d[2]), "+f"(d[3])
                 : "r"(a.x), "r"(a.y), "r"(a.z), "r"(a.w), "r"(b0), "r"(b1));
}

// ---------------- prep: bf16 hi/lo A-fragments (verified in R4-R6) ----------
__global__ void prep_kernel(const float* __restrict__ phi1W1, const float* __restrict__ phi1W2,
                            const float* __restrict__ phiKW1, const float* __restrict__ phiKW2,
                            const float* __restrict__ g1W1,   const float* __restrict__ g1W2,
                            const float* __restrict__ gKW1,   const float* __restrict__ gKW2,
                            const float* __restrict__ g5W1) {
    const int id = blockIdx.x;
    const float* src; int off, KB, type;
    if (id == 0)       { src = phi1W1;              off = OFF_PHI1_W1F;            KB = 1; type = 3; }
    else if (id == 1)  { src = phi1W2;              off = OFF_PHI1_W2F;            KB = 4; type = 0; }
    else if (id < 6)   { int i = id - 2;  src = phiKW1 + i * 64 * 65;  off = OFF_PHIK_W1F + i * 5120; KB = 5; type = 1; }
    else if (id < 10)  { int i = id - 6;  src = phiKW2 + i * 4096;     off = OFF_PHIK_W2F + i * 4096; KB = 4; type = 0; }
    else if (id == 10) { src = g1W1;                off = OFF_G1_W1F;              KB = 5; type = 4; }
    else if (id == 11) { src = g1W2;                off = OFF_G1_W2F;              KB = 4; type = 0; }
    else if (id < 15)  { int i = id - 12; src = gKW1 + i * 64 * 128;   off = OFF_GK_W1F + i * 8192;   KB = 8; type = 5; }
    else if (id < 18)  { int i = id - 15; src = gKW2 + i * 4096;       off = OFF_GK_W2F + i * 4096;   KB = 4; type = 0; }
    else               { src = g5W1;                off = OFF_G5_W1F;              KB = 8; type = 5; }

    const float ninv = -1.0f / 63.0f;
    const int total = KB * 1024;
    for (int e = threadIdx.x; e < total; e += blockDim.x) {
        int strip = e / (KB * 256);
        int rem   = e % (KB * 256);
        int kt = rem / 256;
        int r2 = rem % 256;
        int plane = r2 >> 7;
        int r3 = r2 & 127;
        int lane = r3 >> 2, j = r3 & 3;
        int o  = strip * 16 + (lane >> 2) + 8 * (j & 1);
        int k0 = kt * 16 + (lane & 3) * 2 + 8 * (j >> 1);
        float w0, w1;
        if (type == 0)      { w0 = src[o * 64 + k0];  w1 = src[o * 64 + k0 + 1]; }
        else if (type == 5) { w0 = src[o * 128 + k0]; w1 = src[o * 128 + k0 + 1];
                              if (k0 >= 64) { w0 *= ninv; w1 *= ninv; } }
        else if (type == 1 || type == 4) {
            auto fetch = [&](int c) -> float {
                if (c < 64) {
                    float v = src[o * 65 + 1 + c];
                    return (type == 4) ? v * ninv : v;
                }
                if (c == 64) return src[o * 65];
                return 0.0f;
            };
            w0 = fetch(k0); w1 = fetch(k0 + 1);
        } else {
            w0 = (k0 == 0) ? (src[o * 2] + src[o * 2 + 1]) : 0.0f;
            w1 = 0.0f;
        }
        float h0, l0, h1, l1; split1(w0, h0, l0); split1(w1, h1, l1);
        g_wfrag[off + e] = plane ? pack2(l0, l1) : pack2(h0, h1);
    }
}

// ---------------- cg transpose + pack ----------------------------------------
__global__ void cgt_kernel(const float* __restrict__ cg) {
    const int b = blockIdx.x;
    for (int j = threadIdx.x; j < 4096; j += 256) {
        int a = j >> 6, u = j & 63;
        float v = cg[b * 4096 + u * 64 + a];
        uint32_t bits = __float_as_uint(v);
        float lo = v - __uint_as_float(bits & 0xffff0000u);
        g_cgPh[(b * 64 + a) * 64 + u] = bits >> 16;
        g_cgPl[(b * 64 + a) * 64 + u] = (uint32_t)__bfloat16_as_ushort(__float2bfloat16_rn(lo));
    }
}

// ---------------- sum over a of packed msgs -----------------------------------
__global__ void asum_kernel() {
    const int b = blockIdx.x >> 3;
    const int e = (blockIdx.x & 7) * 256 + threadIdx.x;
    const uint32_t* p0 = g_msgsP + (size_t)b * 262144 + e;
    float s0 = 0.f, s1 = 0.f;
#pragma unroll 4
    for (int a = 0; a < 64; ++a) {
        uint32_t h = p0[(size_t)a * 4096];
        uint32_t l = p0[(size_t)a * 4096 + 2048];
        s0 += __uint_as_float(h << 16) + __uint_as_float(l << 16);
        s1 += __uint_as_float(h & 0xffff0000u) + __uint_as_float(l & 0xffff0000u);
    }
    int pr = e >> 6, u = e & 63;
    g_sums[b * 4096 + (2 * pr) * 64 + u]     = s0;
    g_sums[b * 4096 + (2 * pr + 1) * 64 + u] = s1;
}

// ---------------- per-b precompute: P = bias1 + (Wagg/63)*S -------------------
__global__ void pP_kernel(const float* __restrict__ Wsrc, const float* __restrict__ b1,
                          int CW, int cOff) {
    __shared__ float sWT[64 * 65];
    __shared__ float sS2[4096];
    const int b = blockIdx.x, t = threadIdx.x;
    for (int idx = t; idx < 4096; idx += 256) {
        int o = idx >> 6, c = idx & 63;
        sWT[c * 65 + o] = Wsrc[o * CW + cOff + c] * (1.0f / 63.0f);
        sS2[idx] = g_sums[b * 4096 + idx];
    }
    __syncthreads();
    const int o = t & 63, ublk = t >> 6;
    float acc[16];
    float bv = __ldg(b1 + o);
#pragma unroll
    for (int i = 0; i < 16; ++i) acc[i] = bv;
    const float4* S4 = (const float4*)sS2;
#pragma unroll 4
    for (int c = 0; c < 64; ++c) {
        float w = sWT[c * 65 + o];
#pragma unroll
        for (int i = 0; i < 4; ++i) {
            float4 s = S4[c * 16 + ublk * 4 + i];
            acc[i * 4 + 0] += w * s.x; acc[i * 4 + 1] += w * s.y;
            acc[i * 4 + 2] += w * s.z; acc[i * 4 + 3] += w * s.w;
        }
    }
    float4* P4 = (float4*)(g_P + b * 4096 + o * 64 + ublk * 16);
#pragma unroll
    for (int i = 0; i < 4; ++i)
        P4[i] = make_float4(acc[i * 4], acc[i * 4 + 1], acc[i * 4 + 2], acc[i * 4 + 3]);
}

// ---------------- cp.async prefetch of one slice into an X buffer -------------
template<int MODE, int XR>
__device__ __forceinline__ void prefetch_slice(uint32_t dstH, uint32_t dstL, int ba, int t) {
    const uint32_t* rP = g_rP + (size_t)ba * 4096;
    const uint32_t* mP = g_msgsP + (size_t)ba * 4096;
    const uint32_t* ch = g_cgPh + ba * 64;
    const uint32_t* cl = g_cgPl + ba * 64;
    constexpr int NR = (MODE == 0) ? 1 : (MODE == 3) ? 64 : 33;
    for (int cc = t; cc < 2 * NR * 16; cc += 256) {
        int plane = cc / (NR * 16);
        int rr = cc % (NR * 16);
        int row = rr >> 4, c4 = (rr & 15) * 4;
        const uint32_t* src;
        if (MODE == 0) {
            src = (plane ? cl : ch) + c4;
        } else if (MODE == 3) {
            if (row < 32) src = rP + plane * 2048 + row * 64 + c4;
            else          src = mP + (plane ? 2048 : 0) + (row - 32) * 64 + c4;
        } else {
            const uint32_t* base = (MODE == 1) ? rP : mP;
            if (row < 32) src = base + plane * 2048 + row * 64 + c4;
            else          src = (plane ? cl : ch) + c4;     // row == 32
        }
        uint32_t dst = (plane ? dstL : dstH) + (uint32_t)(row * 72 + c4) * 4u;
        CP_ASYNC16(dst, src);
    }
}

// ---------------- layer kernel (persistent, double-buffered) ------------------
// MODE: 0 phi1, 1 phiK, 2 gamma1, 3 gammaK/gamma5
template<int KB1, int MODE, bool FINAL>
__global__ void __launch_bounds__(256, 2) layer_kernel(const float* __restrict__ b1v,
                                                       const float* __restrict__ b2v,
                                                       int w1off, int w2off,
                                                       const float* __restrict__ w2raw,
                                                       float* __restrict__ dout) {
    constexpr bool RELU2 = (MODE >= 2);
    constexpr bool DB = !FINAL;
    constexpr int XR = (KB1 * 8 < 32) ? 32 : KB1 * 8;
    constexpr int BUFU = 2 * XR * 72;                     // u32 per buffer (both planes)
    extern __shared__ uint32_t sm[];
    uint32_t* sW1f = sm;                                  // KB1*1024
    uint32_t* sX   = sW1f + KB1 * 1024;                   // (DB?2:1) * BUFU
    float*    sS   = (float*)(sX + (DB ? 2 : 1) * BUFU);  // 160
    float*    sH   = sS + 160;                            // 64*66 (FINAL only)

    const int t = threadIdx.x;
    const int warp = t >> 5, lane = t & 31, q = lane & 3, g = lane >> 2;
    const int s = warp >> 1, h2 = warp & 1;
    const int ub = h2 * 32;
    const int o_r = s * 16 + g, o_r8 = o_r + 8;
    const bool geven = ((g & 1) == 0);
    const float inv = 1.0f / 63.0f;

    uint32_t smbase;
    asm("{ .reg .u64 tmp; cvta.to.shared.u64 tmp, %1; cvt.u32.u64 %0, tmp; }"
        : "=r"(smbase) : "l"(sm));
    const uint32_t xbase = smbase + (uint32_t)(KB1 * 1024) * 4u;

    // W1 to smem; W2 fragments to registers
    {
        const uint4* gw1 = (const uint4*)(g_wfrag + w1off);
        uint4* d1 = (uint4*)sW1f;
        for (int i = t; i < KB1 * 256; i += 256) d1[i] = gw1[i];
    }
    uint4 W2h[4], W2l[4];
    if (!FINAL) {
        const uint4* gw2 = (const uint4*)(g_wfrag + w2off);
#pragma unroll
        for (int kt = 0; kt < 4; ++kt) {
            W2h[kt] = gw2[s * 256 + kt * 64 + lane];
            W2l[kt] = gw2[s * 256 + kt * 64 + 32 + lane];
        }
    }
    float bA1 = 0.f, bB1 = 0.f, bA2 = 0.f, bB2 = 0.f;
    if (MODE < 2) { bA1 = __ldg(b1v + o_r); bB1 = __ldg(b1v + o_r8); }
    if (!FINAL)   { bA2 = __ldg(b2v + o_r); bB2 = __ldg(b2v + o_r8); }

    // prezero X buffers (pad rows persist as zero)
    for (int i = t; i < (DB ? 2 : 1) * BUFU; i += 256) sX[i] = 0;
    __syncthreads();

    const int stride = gridDim.x;
    int o = 0;
    if (DB) {
        if ((int)blockIdx.x < NBA)
            prefetch_slice<MODE, XR>(xbase, xbase + XR * 72 * 4, blockIdx.x, t);
        CP_COMMIT();
    }

    for (int ba = blockIdx.x; ba < NBA; ba += stride) {
        const int b = ba >> 6;
        if (DB) {
            int nxt = ba + stride;
            uint32_t nb = xbase + (uint32_t)((o ^ 1) * BUFU) * 4u;
            if (nxt < NBA) prefetch_slice<MODE, XR>(nb, nb + XR * 72 * 4, nxt, t);
            CP_COMMIT();
            CP_WAIT1();
        } else {
            prefetch_slice<MODE, XR>(xbase, xbase + XR * 72 * 4, ba, t);
            CP_COMMIT();
            CP_WAIT0();
        }
        __syncthreads();

        uint32_t* bH = sX + o * BUFU;
        uint32_t* bL = bH + XR * 72;

        // early P loads (consumed post-mma)
        float2 pa[4], pb[4];
        if (MODE >= 2) {
            const float* Pb = g_P + b * 4096;
#pragma unroll
            for (int nt = 0; nt < 4; ++nt) {
                int u0 = ub + nt * 8 + q * 2;
                pa[nt] = __ldg((const float2*)(Pb + o_r * 64 + u0));
                pb[nt] = __ldg((const float2*)(Pb + o_r8 * 64 + u0));
            }
        }

        // ---- conv1 ----
        float acc[4][4];
#pragma unroll
        for (int nt = 0; nt < 4; ++nt)
#pragma unroll
            for (int j = 0; j < 4; ++j) acc[nt][j] = 0.f;
        {
            const uint4* A1 = (const uint4*)sW1f + s * (KB1 * 64);
#pragma unroll
            for (int kt = 0; kt < KB1; ++kt) {
                uint4 Ah = A1[kt * 64 + lane];
                uint4 Al = A1[kt * 64 + 32 + lane];
                const uint32_t* xh0 = bH + (kt * 8 + q) * 72 + ub + g;
                const uint32_t* xh1 = bH + (kt * 8 + 4 + q) * 72 + ub + g;
                const uint32_t* xl0 = bL + (kt * 8 + q) * 72 + ub + g;
                const uint32_t* xl1 = bL + (kt * 8 + 4 + q) * 72 + ub + g;
                uint32_t bh0[4], bh1[4], bl0[4], bl1[4];
#pragma unroll
                for (int nt = 0; nt < 4; ++nt) {
                    bh0[nt] = xh0[nt * 8]; bh1[nt] = xh1[nt * 8];
                    bl0[nt] = xl0[nt * 8]; bl1[nt] = xl1[nt * 8];
                }
#pragma unroll
                for (int nt = 0; nt < 4; ++nt) {
                    mma16816(acc[nt], Ah, bh0[nt], bh1[nt]);
                    mma16816(acc[nt], Ah, bl0[nt], bl1[nt]);
                    mma16816(acc[nt], Al, bh0[nt], bh1[nt]);
                }
            }
        }
        // bias/P (post-mma) + relu + colsum
        if (MODE >= 2) {
#pragma unroll
            for (int nt = 0; nt < 4; ++nt) {
                acc[nt][0] += pa[nt].x; acc[nt][1] += pa[nt].y;
                acc[nt][2] += pb[nt].x; acc[nt][3] += pb[nt].y;
            }
        } else {
#pragma unroll
            for (int nt = 0; nt < 4; ++nt) {
                acc[nt][0] += bA1; acc[nt][1] += bA1;
                acc[nt][2] += bB1; acc[nt][3] += bB1;
            }
        }
#pragma unroll
        for (int nt = 0; nt < 4; ++nt)
#pragma unroll
            for (int j = 0; j < 4; ++j) acc[nt][j] = fmaxf(acc[nt][j], 0.0f);
        {
            float sA = 0.f, sB = 0.f;
#pragma unroll
            for (int nt = 0; nt < 4; ++nt) { sA += acc[nt][0] + acc[nt][1]; sB += acc[nt][2] + acc[nt][3]; }
            sA += __shfl_xor_sync(0xffffffffu, sA, 1); sA += __shfl_xor_sync(0xffffffffu, sA, 2);
            sB += __shfl_xor_sync(0xffffffffu, sB, 1); sB += __shfl_xor_sync(0xffffffffu, sB, 2);
            if (q == 0) { sS[h2 * 80 + o_r] = sA; sS[h2 * 80 + o_r8] = sB; }
        }
        __syncthreads();
        float SA = sS[o_r] + sS[80 + o_r];
        float SB = sS[o_r8] + sS[80 + o_r8];

        if (!FINAL) {
            // post + pair-pack into current buffer rows 0..31
#pragma unroll
            for (int nt = 0; nt < 4; ++nt) {
                float t0, t1, t2, t3;
                if (s >= 2) {
                    t0 = (SA - acc[nt][0]) * inv; t1 = (SA - acc[nt][1]) * inv;
                    t2 = (SB - acc[nt][2]) * inv; t3 = (SB - acc[nt][3]) * inv;
                } else { t0 = acc[nt][0]; t1 = acc[nt][1]; t2 = acc[nt][2]; t3 = acc[nt][3]; }
                float p0 = __shfl_xor_sync(0xffffffffu, t0, 4);
                float p1 = __shfl_xor_sync(0xffffffffu, t1, 4);
                float p2 = __shfl_xor_sync(0xffffffffu, t2, 4);
                float p3 = __shfl_xor_sync(0xffffffffu, t3, 4);
                float v0a, v0b, v1a, v1b; int c2;
                if (geven) { c2 = (s * 16 + g) >> 1;          v0a = t0; v0b = p0; v1a = t1; v1b = p1; }
                else       { c2 = (s * 16 + 8 + g - 1) >> 1;  v0a = p2; v0b = t2; v1a = p3; v1b = t3; }
                uint32_t ba0 = __float_as_uint(v0a), bb0 = __float_as_uint(v0b);
                uint32_t ba1 = __float_as_uint(v1a), bb1 = __float_as_uint(v1b);
                uint32_t ph0 = __byte_perm(ba0, bb0, 0x7632);
                uint32_t ph1 = __byte_perm(ba1, bb1, 0x7632);
                float l0a = v0a - __uint_as_float(ba0 & 0xffff0000u);
                float l0b = v0b - __uint_as_float(bb0 & 0xffff0000u);
                float l1a = v1a - __uint_as_float(ba1 & 0xffff0000u);
                float l1b = v1b - __uint_as_float(bb1 & 0xffff0000u);
                uint32_t pl0 = pack2(l0a, l0b);
                uint32_t pl1 = pack2(l1a, l1b);
                int u0 = ub + nt * 8 + q * 2;
                bH[c2 * 72 + u0] = ph0; bH[c2 * 72 + u0 + 1] = ph1;
                bL[c2 * 72 + u0] = pl0; bL[c2 * 72 + u0 + 1] = pl1;
            }
            __syncthreads();

            // ---- conv2 (KB=4, W2 in registers) ----
            float a2[4][4];
#pragma unroll
            for (int nt = 0; nt < 4; ++nt)
#pragma unroll
                for (int j = 0; j < 4; ++j) a2[nt][j] = 0.f;
#pragma unroll
            for (int kt = 0; kt < 4; ++kt) {
                const uint32_t* xh0 = bH + (kt * 8 + q) * 72 + ub + g;
                const uint32_t* xh1 = bH + (kt * 8 + 4 + q) * 72 + ub + g;
                const uint32_t* xl0 = bL + (kt * 8 + q) * 72 + ub + g;
                const uint32_t* xl1 = bL + (kt * 8 + 4 + q) * 72 + ub + g;
                uint32_t bh0[4], bh1[4], bl0[4], bl1[4];
#pragma unroll
                for (int nt = 0; nt < 4; ++nt) {
                    bh0[nt] = xh0[nt * 8]; bh1[nt] = xh1[nt * 8];
                    bl0[nt] = xl0[nt * 8]; bl1[nt] = xl1[nt * 8];
                }
#pragma unroll
                for (int nt = 0; nt < 4; ++nt) {
                    mma16816(a2[nt], W2h[kt], bh0[nt], bh1[nt]);
                    mma16816(a2[nt], W2h[kt], bl0[nt], bl1[nt]);
                    mma16816(a2[nt], W2l[kt], bh0[nt], bh1[nt]);
                }
            }
#pragma unroll
            for (int nt = 0; nt < 4; ++nt) {
                a2[nt][0] += bA2; a2[nt][1] += bA2;
                a2[nt][2] += bB2; a2[nt][3] += bB2;
            }
            if (RELU2) {
#pragma unroll
                for (int nt = 0; nt < 4; ++nt)
#pragma unroll
                    for (int j = 0; j < 4; ++j) a2[nt][j] = fmaxf(a2[nt][j], 0.0f);
            }
            float s2A = 0.f, s2B = 0.f;
#pragma unroll
            for (int nt = 0; nt < 4; ++nt) { s2A += a2[nt][0] + a2[nt][1]; s2B += a2[nt][2] + a2[nt][3]; }
            s2A += __shfl_xor_sync(0xffffffffu, s2A, 1); s2A += __shfl_xor_sync(0xffffffffu, s2A, 2);
            s2B += __shfl_xor_sync(0xffffffffu, s2B, 1); s2B += __shfl_xor_sync(0xffffffffu, s2B, 2);
            if (q == 0) { sS[h2 * 80 + o_r] = s2A; sS[h2 * 80 + o_r8] = s2B; }
            __syncthreads();
            float S2A = sS[o_r] + sS[80 + o_r];
            float S2B = sS[o_r8] + sS[80 + o_r8];

            uint32_t* gout = (RELU2 ? g_rP : g_msgsP) + (size_t)ba * 4096;
#pragma unroll
            for (int nt = 0; nt < 4; ++nt) {
                float t0, t1, t2, t3;
                if (s >= 2) {
                    t0 = (S2A - a2[nt][0]) * inv; t1 = (S2A - a2[nt][1]) * inv;
                    t2 = (S2B - a2[nt][2]) * inv; t3 = (S2B - a2[nt][3]) * inv;
                } else { t0 = a2[nt][0]; t1 = a2[nt][1]; t2 = a2[nt][2]; t3 = a2[nt][3]; }
                float p0 = __shfl_xor_sync(0xffffffffu, t0, 4);
                float p1 = __shfl_xor_sync(0xffffffffu, t1, 4);
                float p2 = __shfl_xor_sync(0xffffffffu, t2, 4);
                float p3 = __shfl_xor_sync(0xffffffffu, t3, 4);
                float v0a, v0b, v1a, v1b; int c2;
                if (geven) { c2 = (s * 16 + g) >> 1;          v0a = t0; v0b = p0; v1a = t1; v1b = p1; }
                else       { c2 = (s * 16 + 8 + g - 1) >> 1;  v0a = p2; v0b = t2; v1a = p3; v1b = t3; }
                uint32_t ba0 = __float_as_uint(v0a), bb0 = __float_as_uint(v0b);
                uint32_t ba1 = __float_as_uint(v1a), bb1 = __float_as_uint(v1b);
                uint32_t ph0 = __byte_perm(ba0, bb0, 0x7632);
                uint32_t ph1 = __byte_perm(ba1, bb1, 0x7632);
                float l0a = v0a - __uint_as_float(ba0 & 0xffff0000u);
                float l0b = v0b - __uint_as_float(bb0 & 0xffff0000u);
                float l1a = v1a - __uint_as_float(ba1 & 0xffff0000u);
                float l1b = v1b - __uint_as_float(bb1 & 0xffff0000u);
                uint32_t pl0 = pack2(l0a, l0b);
                uint32_t pl1 = pack2(l1a, l1b);
                int u0 = ub + nt * 8 + q * 2;
                uint2 vh; vh.x = ph0; vh.y = ph1;
                uint2 vl; vl.x = pl0; vl.y = pl1;
                *(uint2*)(gout + c2 * 64 + u0) = vh;
                *(uint2*)(gout + 2048 + c2 * 64 + u0) = vl;
            }
            o ^= 1;
        } else {
            // FINAL: post-transformed H to sH, then 1x64 GEMV
#pragma unroll
            for (int nt = 0; nt < 4; ++nt) {
                int u0 = ub + nt * 8 + q * 2;
                float2 vA, vB;
                if (s >= 2) {
                    vA.x = (SA - acc[nt][0]) * inv; vA.y = (SA - acc[nt][1]) * inv;
                    vB.x = (SB - acc[nt][2]) * inv; vB.y = (SB - acc[nt][3]) * inv;
                } else { vA.x = acc[nt][0]; vA.y = acc[nt][1]; vB.x = acc[nt][2]; vB.y = acc[nt][3]; }
                *(float2*)(sH + o_r * 66 + u0)  = vA;
                *(float2*)(sH + o_r8 * 66 + u0) = vB;
            }
            __syncthreads();
            const int u = t >> 2, part = t & 3;
            float sv = 0.0f;
            const int c0 = part * 16;
#pragma unroll
            for (int c = c0; c < c0 + 16; ++c)
                sv = fmaf(__ldg(w2raw + c), sH[c * 66 + u], sv);
            sv += __shfl_xor_sync(0xffffffffu, sv, 1);
            sv += __shfl_xor_sync(0xffffffffu, sv, 2);
            if (part == 0)
                dout[b * 4096 + u * 64 + (ba & 63)] = sv + __ldg(b2v);
            __syncthreads();
        }
    }
}

// ---------------- launch -----------------------------------------------------
extern "C" void kernel_launch(void* const* d_in, const int* in_sizes, int n_in,
                              void* d_out, int out_size) {
    (void)in_sizes; (void)n_in; (void)out_size;
    const float* cg      = (const float*)d_in[0];
    const float* phi1_W1 = (const float*)d_in[1];
    const float* phi1_b1 = (const float*)d_in[2];
    const float* phi1_W2 = (const float*)d_in[3];
    const float* phi1_b2 = (const float*)d_in[4];
    const float* phiK_W1 = (const float*)d_in[5];
    const float* phiK_b1 = (const float*)d_in[6];
    const float* phiK_W2 = (const float*)d_in[7];
    const float* phiK_b2 = (const float*)d_in[8];
    const float* g1_W1   = (const float*)d_in[9];
    const float* g1_b1   = (const float*)d_in[10];
    const float* g1_W2   = (const float*)d_in[11];
    const float* g1_b2   = (const float*)d_in[12];
    const float* gK_W1   = (const float*)d_in[13];
    const float* gK_b1   = (const float*)d_in[14];
    const float* gK_W2   = (const float*)d_in[15];
    const float* gK_b2   = (const float*)d_in[16];
    const float* g5_W1   = (const float*)d_in[17];
    const float* g5_b1   = (const float*)d_in[18];
    const float* g5_W2   = (const float*)d_in[19];
    const float* g5_b2   = (const float*)d_in[20];
    float* out = (float*)d_out;

    auto smem_bytes = [](int KB1, bool fin) {
        int XR = (KB1 * 8 < 32) ? 32 : KB1 * 8;
        int nbuf = fin ? 1 : 2;
        int u32s = KB1 * 1024 + nbuf * 2 * XR * 72 + 160 + (fin ? 64 * 66 : 0);
        return u32s * 4;
    };
    const int SM1 = smem_bytes(1, false);
    const int SM5 = smem_bytes(5, false);
    const int SM8 = smem_bytes(8, false);
    const int SMF = smem_bytes(8, true);

    cudaFuncSetAttribute(layer_kernel<1, 0, false>, cudaFuncAttributeMaxDynamicSharedMemorySize, SM1);
    cudaFuncSetAttribute(layer_kernel<5, 1, false>, cudaFuncAttributeMaxDynamicSharedMemorySize, SM5);
    cudaFuncSetAttribute(layer_kernel<5, 2, false>, cudaFuncAttributeMaxDynamicSharedMemorySize, SM5);
    cudaFuncSetAttribute(layer_kernel<8, 3, false>, cudaFuncAttributeMaxDynamicSharedMemorySize, SM8);
    cudaFuncSetAttribute(layer_kernel<8, 3, true>,  cudaFuncAttributeMaxDynamicSharedMemorySize, SMF);

    prep_kernel<<<19, 256>>>(phi1_W1, phi1_W2, phiK_W1, phiK_W2, g1_W1, g1_W2, gK_W1, gK_W2, g5_W1);
    cgt_kernel<<<128, 256>>>(cg);

    const int G = 296;

    layer_kernel<1, 0, false><<<G, 256, SM1>>>(phi1_b1, phi1_b2, OFF_PHI1_W1F, OFF_PHI1_W2F, nullptr, nullptr);
    asum_kernel<<<1024, 256>>>();
    pP_kernel<<<128, 256>>>(g1_W1, g1_b1, 65, 1);
    layer_kernel<5, 2, false><<<G, 256, SM5>>>(nullptr, g1_b2, OFF_G1_W1F, OFF_G1_W2F, nullptr, nullptr);

    for (int i = 0; i < 4; ++i) {
        layer_kernel<5, 1, false><<<G, 256, SM5>>>(phiK_b1 + i * 64, phiK_b2 + i * 64,
                                                   OFF_PHIK_W1F + i * 5120, OFF_PHIK_W2F + i * 4096,
                                                   nullptr, nullptr);
        asum_kernel<<<1024, 256>>>();
        if (i < 3) {
            pP_kernel<<<128, 256>>>(gK_W1 + i * 8192, gK_b1 + i * 64, 128, 64);
            layer_kernel<8, 3, false><<<G, 256, SM8>>>(nullptr, gK_b2 + i * 64,
                                                       OFF_GK_W1F + i * 8192, OFF_GK_W2F + i * 4096,
                                                       nullptr, nullptr);
        } else {
            pP_kernel<<<128, 256>>>(g5_W1, g5_b1, 128, 64);
            layer_kernel<8, 3, true><<<G, 256, SMF>>>(nullptr, g5_b2,
                                                      OFF_G5_W1F, 0, g5_W2, out);
        }
    }
}